// round 1
// baseline (speedup 1.0000x reference)
#include <cuda_runtime.h>
#include <cuda_bf16.h>
#include <math.h>

// ---------------- problem constants ----------------
#define BB 8
#define TQ 8
#define TP 447
#define TC 1500
#define DD 1280
#define HH 20
#define DH 64
#define DFF 5120
#define MM 64              // B*TQ rows
#define TK_SELF (TP + TQ)  // 455

// ---------------- scratch (device globals; no allocation allowed) ----------------
__device__ float g_xl_[MM * DD];
__device__ float g_q_[MM * DD];
__device__ float g_attn_[MM * DD];
__device__ float g_x1_[MM * DD];
__device__ float g_h_[MM * DFF];
__device__ float g_part_[4 * MM * DFF];   // max split-K partials (4 x 64 x 5120)

// ---------------- f32x2 helpers ----------------
__device__ __forceinline__ unsigned long long pk2(float lo, float hi) {
    unsigned long long r;
    asm("mov.b64 %0, {%1,%2};" : "=l"(r) : "f"(lo), "f"(hi));
    return r;
}
__device__ __forceinline__ void fma2(unsigned long long& acc, unsigned long long a,
                                     unsigned long long b) {
    asm("fma.rn.f32x2 %0, %1, %2, %0;" : "+l"(acc) : "l"(a), "l"(b));
}
union F4U2 { float4 f; unsigned long long u[2]; };
union U2F2 { unsigned long long u; float2 f; };

// ---------------- LayerNorm: one block per row ----------------
__global__ __launch_bounds__(256) void ln_kernel(const float* __restrict__ x,
                                                 const float* __restrict__ w,
                                                 const float* __restrict__ b,
                                                 float* __restrict__ out) {
    int row = blockIdx.x;
    const float* xr = x + (size_t)row * DD;
    __shared__ float red0[32], red1[32];
    float s = 0.f, s2 = 0.f;
    for (int i = threadIdx.x; i < DD; i += 256) {
        float v = xr[i];
        s += v;
        s2 += v * v;
    }
    for (int o = 16; o; o >>= 1) {
        s += __shfl_xor_sync(~0u, s, o);
        s2 += __shfl_xor_sync(~0u, s2, o);
    }
    int lane = threadIdx.x & 31, wid = threadIdx.x >> 5;
    if (lane == 0) { red0[wid] = s; red1[wid] = s2; }
    __syncthreads();
    if (wid == 0) {
        s = (lane < 8) ? red0[lane] : 0.f;
        s2 = (lane < 8) ? red1[lane] : 0.f;
        for (int o = 4; o; o >>= 1) {
            s += __shfl_xor_sync(~0u, s, o);
            s2 += __shfl_xor_sync(~0u, s2, o);
        }
        if (lane == 0) { red0[0] = s; red1[0] = s2; }
    }
    __syncthreads();
    float m = red0[0] * (1.f / DD);
    float var = red1[0] * (1.f / DD) - m * m;
    float inv = rsqrtf(var + 1e-5f);
    for (int i = threadIdx.x; i < DD; i += 256) {
        out[(size_t)row * DD + i] = (xr[i] - m) * inv * w[i] + b[i];
    }
}

// ---------------- split-K GEMM: C_part[z] = A[64,Kchunk] @ W[Kchunk,N] ----------------
// grid: (N/64, 1, KSPLIT); block 256. Each thread: 8 rows x 2 cols via f32x2.
__global__ __launch_bounds__(256) void gemm_splitk(const float* __restrict__ A,
                                                   const float* __restrict__ W,
                                                   float* __restrict__ part,
                                                   int K, int N, int kchunk) {
    __shared__ float As[16][64];   // k-major
    __shared__ float Ws[16][64];
    int n0 = blockIdx.x * 64;
    int z = blockIdx.z;
    int k0 = z * kchunk;
    int kend = min(K, k0 + kchunk);
    int tid = threadIdx.x;
    int lane = tid & 31;
    int wid = tid >> 5;        // row group: rows wid*8 .. wid*8+7
    int c0 = lane * 2;         // cols n0+c0, n0+c0+1

    unsigned long long acc[4][2];
#pragma unroll
    for (int p = 0; p < 4; p++) { acc[p][0] = 0ull; acc[p][1] = 0ull; }

    for (int kk = k0; kk < kend; kk += 16) {
        {   // stage A (transpose to k-major)
            int r = tid >> 2;
            int cb = (tid & 3) * 4;
            float4 av = *(const float4*)(A + (size_t)r * K + kk + cb);
            As[cb + 0][r] = av.x; As[cb + 1][r] = av.y;
            As[cb + 2][r] = av.z; As[cb + 3][r] = av.w;
        }
        {   // stage W (direct)
            int c = tid >> 4;
            int col = (tid & 15) * 4;
            *(float4*)&Ws[c][col] = *(const float4*)(W + (size_t)(kk + c) * N + n0 + col);
        }
        __syncthreads();
#pragma unroll
        for (int k = 0; k < 16; k++) {
            float2 wv = *(const float2*)&Ws[k][c0];
            unsigned long long w0 = pk2(wv.x, wv.x);
            unsigned long long w1 = pk2(wv.y, wv.y);
            F4U2 a01, a23;
            a01.f = *(const float4*)&As[k][wid * 8];
            a23.f = *(const float4*)&As[k][wid * 8 + 4];
            fma2(acc[0][0], a01.u[0], w0); fma2(acc[0][1], a01.u[0], w1);
            fma2(acc[1][0], a01.u[1], w0); fma2(acc[1][1], a01.u[1], w1);
            fma2(acc[2][0], a23.u[0], w0); fma2(acc[2][1], a23.u[0], w1);
            fma2(acc[3][0], a23.u[1], w0); fma2(acc[3][1], a23.u[1], w1);
        }
        __syncthreads();
    }
    float* po = part + (size_t)z * MM * N;
#pragma unroll
    for (int p = 0; p < 4; p++) {
        U2F2 v0, v1;
        v0.u = acc[p][0];   // {C[r0][c0], C[r1][c0]}
        v1.u = acc[p][1];   // {C[r0][c0+1], C[r1][c0+1]}
        int r0 = wid * 8 + 2 * p;
        *(float2*)&po[(size_t)r0 * N + n0 + c0] = make_float2(v0.f.x, v1.f.x);
        *(float2*)&po[(size_t)(r0 + 1) * N + n0 + c0] = make_float2(v0.f.y, v1.f.y);
    }
}

// ---------------- reduce partials + epilogue ----------------
__global__ __launch_bounds__(256) void reduce_epi(const float* __restrict__ part, int nz,
                                                  int MN, int N,
                                                  const float* __restrict__ bias,
                                                  const float* __restrict__ res,
                                                  float* __restrict__ out, int dogelu) {
    int i = blockIdx.x * 256 + threadIdx.x;
    if (i >= MN) return;
    float s = 0.f;
    for (int z = 0; z < nz; z++) s += part[(size_t)z * MN + i];
    if (bias) s += bias[i % N];
    if (dogelu) s = 0.5f * s * (1.f + erff(s * 0.70710678118654752440f));
    if (res) s += res[i];
    out[i] = s;
}

// ---------------- attention: one block per (b,h) ----------------
#define SCPITCH 1504
#define ATTN_SMEM_FLOATS (8 * SCPITCH + 8 * 64 + 32 * 68 + 8 * 8 * 64 + 8)
#define ATTN_SMEM_BYTES (ATTN_SMEM_FLOATS * 4)

__global__ __launch_bounds__(256) void attn_kernel(const float* __restrict__ q,
                                                   const float* __restrict__ kcache,
                                                   const float* __restrict__ vcache,
                                                   const float* __restrict__ knew,
                                                   const float* __restrict__ vnew,
                                                   const float* __restrict__ mask,
                                                   float* __restrict__ outbuf,
                                                   int Tk, int Tc) {
    extern __shared__ float smem[];
    float* sc = smem;                           // [8][SCPITCH]
    float* qs = sc + 8 * SCPITCH;               // [8][64]
    float* kt = qs + 8 * 64;                    // [32][68]
    float* red = kt + 32 * 68;                  // [8 warps][8 q][64]
    float* rowsum = red + 8 * 8 * 64;           // [8]

    int h = blockIdx.x, b = blockIdx.y;
    int tid = threadIdx.x, lane = tid & 31, w = tid >> 5;
    const float sclq = 0.125f;  // DH^-0.5 folded into q

    // load q (scaled)
    for (int i = tid; i < 512; i += 256) {
        int qi = i >> 6, d = i & 63;
        qs[qi * 64 + d] = q[(size_t)(b * TQ + qi) * DD + h * DH + d] * sclq;
    }
    __syncthreads();

    // ---- pass 1: scores ----
    for (int kk = 0; kk < Tk; kk += 32) {
        int nk = min(32, Tk - kk);
        for (int i = tid; i < nk * 8; i += 256) {
            int key = kk + (i >> 3);
            int c = (i & 7) * 8;
            const float* kr = (key < Tc)
                ? (kcache + ((size_t)b * Tc + key) * DD + h * DH)
                : (knew + (size_t)(b * TQ + (key - Tc)) * DD + h * DH);
            float4 va = *(const float4*)(kr + c);
            float4 vb = *(const float4*)(kr + c + 4);
            *(float4*)&kt[(i >> 3) * 68 + c] = va;
            *(float4*)&kt[(i >> 3) * 68 + c + 4] = vb;
        }
        __syncthreads();
        if (lane < nk) {
            const float* kr = &kt[lane * 68];
            const float* qr = &qs[w * 64];
            float s = 0.f;
#pragma unroll
            for (int d = 0; d < 64; d += 4) {
                float4 qv = *(const float4*)(qr + d);
                float4 kv = *(const float4*)(kr + d);
                s += qv.x * kv.x + qv.y * kv.y + qv.z * kv.z + qv.w * kv.w;
            }
            if (mask) s += mask[w * Tk + kk + lane];
            sc[w * SCPITCH + kk + lane] = s;
        }
        __syncthreads();
    }

    // ---- softmax (warp w owns q row w) ----
    {
        float* sr = &sc[w * SCPITCH];
        float m = -1e30f;
        for (int k = lane; k < Tk; k += 32) m = fmaxf(m, sr[k]);
        for (int o = 16; o; o >>= 1) m = fmaxf(m, __shfl_xor_sync(~0u, m, o));
        float ssum = 0.f;
        for (int k = lane; k < Tk; k += 32) {
            float e = __expf(sr[k] - m);
            sr[k] = e;
            ssum += e;
        }
        for (int o = 16; o; o >>= 1) ssum += __shfl_xor_sync(~0u, ssum, o);
        if (lane == 0) rowsum[w] = ssum;
    }
    __syncthreads();

    // ---- pass 2: AV (warp w takes keys k ≡ w mod 8; lane owns dims 2l,2l+1) ----
    float acc[8][2];
#pragma unroll
    for (int qi = 0; qi < 8; qi++) { acc[qi][0] = 0.f; acc[qi][1] = 0.f; }
    for (int k = w; k < Tk; k += 8) {
        const float* vr = (k < Tc)
            ? (vcache + ((size_t)b * Tc + k) * DD + h * DH)
            : (vnew + (size_t)(b * TQ + (k - Tc)) * DD + h * DH);
        float2 v2 = *(const float2*)(vr + 2 * lane);
#pragma unroll
        for (int qi = 0; qi < 8; qi++) {
            float p = sc[qi * SCPITCH + k];
            acc[qi][0] += p * v2.x;
            acc[qi][1] += p * v2.y;
        }
    }
#pragma unroll
    for (int qi = 0; qi < 8; qi++) {
        red[(w * 8 + qi) * 64 + 2 * lane] = acc[qi][0];
        red[(w * 8 + qi) * 64 + 2 * lane + 1] = acc[qi][1];
    }
    __syncthreads();
    for (int i = tid; i < 512; i += 256) {
        int qi = i >> 6, d = i & 63;
        float s = 0.f;
#pragma unroll
        for (int ww = 0; ww < 8; ww++) s += red[(ww * 8 + qi) * 64 + d];
        outbuf[(size_t)(b * TQ + qi) * DD + h * DH + d] = s / rowsum[qi];
    }
}

// ---------------- host orchestration ----------------
extern "C" void kernel_launch(void* const* d_in, const int* in_sizes, int n_in,
                              void* d_out, int out_size) {
    const float* x            = (const float*)d_in[0];
    const float* self_k_cache = (const float*)d_in[1];
    const float* self_v_cache = (const float*)d_in[2];
    const float* cross_k      = (const float*)d_in[3];
    const float* cross_v      = (const float*)d_in[4];
    const float* mask         = (const float*)d_in[5];
    const float* attn_wq = (const float*)d_in[6];
    const float* attn_bq = (const float*)d_in[7];
    const float* attn_wk = (const float*)d_in[8];
    const float* attn_wv = (const float*)d_in[9];
    const float* attn_bv = (const float*)d_in[10];
    const float* attn_wo = (const float*)d_in[11];
    const float* attn_bo = (const float*)d_in[12];
    const float* cross_wq = (const float*)d_in[13];
    const float* cross_bq = (const float*)d_in[14];
    const float* cross_wo = (const float*)d_in[15];
    const float* cross_bo = (const float*)d_in[16];
    const float* attn_ln_w = (const float*)d_in[17];
    const float* attn_ln_b = (const float*)d_in[18];
    const float* cross_ln_w = (const float*)d_in[19];
    const float* cross_ln_b = (const float*)d_in[20];
    const float* mlp_ln_w = (const float*)d_in[21];
    const float* mlp_ln_b = (const float*)d_in[22];
    const float* mlp_w1 = (const float*)d_in[23];
    const float* mlp_b1 = (const float*)d_in[24];
    const float* mlp_w2 = (const float*)d_in[25];
    const float* mlp_b2 = (const float*)d_in[26];

    float* out_x  = (float*)d_out;
    float* out_k1 = out_x + MM * DD;
    float* out_v1 = out_k1 + MM * DD;

    float *g_xl, *g_q, *g_attn, *g_x1, *g_h, *g_part;
    cudaGetSymbolAddress((void**)&g_xl, g_xl_);
    cudaGetSymbolAddress((void**)&g_q, g_q_);
    cudaGetSymbolAddress((void**)&g_attn, g_attn_);
    cudaGetSymbolAddress((void**)&g_x1, g_x1_);
    cudaGetSymbolAddress((void**)&g_h, g_h_);
    cudaGetSymbolAddress((void**)&g_part, g_part_);

    cudaFuncSetAttribute(attn_kernel, cudaFuncAttributeMaxDynamicSharedMemorySize,
                         ATTN_SMEM_BYTES);

    const int MN_D = MM * DD;        // 81920
    const int MN_F = MM * DFF;       // 327680
    dim3 blk(256);
    dim3 gemmD(DD / 64, 1, 8);       // N=1280, K split 8
    dim3 gemmF1(DFF / 64, 1, 4);     // N=5120, K=1280 split 4
    dim3 gemmF2(DD / 64, 1, 8);      // N=1280, K=5120 split 8
    int redD = (MN_D + 255) / 256;
    int redF = (MN_F + 255) / 256;

    // --- self-attention block ---
    ln_kernel<<<MM, blk>>>(x, attn_ln_w, attn_ln_b, g_xl);

    gemm_splitk<<<gemmD, blk>>>(g_xl, attn_wq, g_part, DD, DD, 160);
    reduce_epi<<<redD, blk>>>(g_part, 8, MN_D, DD, attn_bq, nullptr, g_q, 0);

    gemm_splitk<<<gemmD, blk>>>(g_xl, attn_wk, g_part, DD, DD, 160);
    reduce_epi<<<redD, blk>>>(g_part, 8, MN_D, DD, nullptr, nullptr, out_k1, 0);

    gemm_splitk<<<gemmD, blk>>>(g_xl, attn_wv, g_part, DD, DD, 160);
    reduce_epi<<<redD, blk>>>(g_part, 8, MN_D, DD, attn_bv, nullptr, out_v1, 0);

    attn_kernel<<<dim3(HH, BB), blk, ATTN_SMEM_BYTES>>>(
        g_q, self_k_cache, self_v_cache, out_k1, out_v1, mask, g_attn, TK_SELF, TP);

    gemm_splitk<<<gemmD, blk>>>(g_attn, attn_wo, g_part, DD, DD, 160);
    reduce_epi<<<redD, blk>>>(g_part, 8, MN_D, DD, attn_bo, x, g_x1, 0);

    // --- cross-attention block ---
    ln_kernel<<<MM, blk>>>(g_x1, cross_ln_w, cross_ln_b, g_xl);

    gemm_splitk<<<gemmD, blk>>>(g_xl, cross_wq, g_part, DD, DD, 160);
    reduce_epi<<<redD, blk>>>(g_part, 8, MN_D, DD, cross_bq, nullptr, g_q, 0);

    attn_kernel<<<dim3(HH, BB), blk, ATTN_SMEM_BYTES>>>(
        g_q, cross_k, cross_v, nullptr, nullptr, nullptr, g_attn, TC, TC);

    gemm_splitk<<<gemmD, blk>>>(g_attn, cross_wo, g_part, DD, DD, 160);
    reduce_epi<<<redD, blk>>>(g_part, 8, MN_D, DD, cross_bo, g_x1, out_x, 0);

    // --- MLP block ---
    ln_kernel<<<MM, blk>>>(out_x, mlp_ln_w, mlp_ln_b, g_xl);

    gemm_splitk<<<gemmF1, blk>>>(g_xl, mlp_w1, g_part, DD, DFF, 320);
    reduce_epi<<<redF, blk>>>(g_part, 4, MN_F, DFF, mlp_b1, nullptr, g_h, 1);

    gemm_splitk<<<gemmF2, blk>>>(g_h, mlp_w2, g_part, DFF, DD, 640);
    reduce_epi<<<redD, blk>>>(g_part, 8, MN_D, DD, mlp_b2, out_x, out_x, 0);
}

// round 3
// speedup vs baseline: 1.3188x; 1.3188x over previous
#include <cuda_runtime.h>
#include <cuda_bf16.h>
#include <math.h>

// ---------------- problem constants ----------------
#define BB 8
#define TQ 8
#define TP 447
#define TC 1500
#define DD 1280
#define HH 20
#define DH 64
#define DFF 5120
#define MM 64              // B*TQ rows
#define TK_SELF (TP + TQ)  // 455

// ---------------- scratch (device globals; no allocation allowed) ----------------
__device__ float g_xl_[MM * DD];
__device__ float g_q_[MM * DD];
__device__ float g_attn_[MM * DD];
__device__ float g_x1_[MM * DD];
__device__ float g_h_[MM * DFF];
__device__ float g_part_[5242880];          // split-K partials (max 21 MB)
__device__ float g_apacc_[4 * BB * HH * TQ * DH];  // attn split partial acc
__device__ float g_aml_[4 * BB * HH * 16];         // attn split (m,l) per q

// ---------------- f32x2 helpers ----------------
__device__ __forceinline__ unsigned long long pk2(float lo, float hi) {
    unsigned long long r;
    asm("mov.b64 %0, {%1,%2};" : "=l"(r) : "f"(lo), "f"(hi));
    return r;
}
__device__ __forceinline__ void fma2(unsigned long long& acc, unsigned long long a,
                                     unsigned long long b) {
    asm("fma.rn.f32x2 %0, %1, %2, %0;" : "+l"(acc) : "l"(a), "l"(b));
}
union F4U2 { float4 f; unsigned long long u[2]; };
union U2F2 { unsigned long long u; float2 f; };

// ---------------- LayerNorm: one block per row ----------------
__global__ __launch_bounds__(256) void ln_kernel(const float* __restrict__ x,
                                                 const float* __restrict__ w,
                                                 const float* __restrict__ b,
                                                 float* __restrict__ out) {
    int row = blockIdx.x;
    const float* xr = x + (size_t)row * DD;
    __shared__ float red0[32], red1[32];
    float s = 0.f, s2 = 0.f;
    for (int i = threadIdx.x; i < DD; i += 256) {
        float v = xr[i];
        s += v;
        s2 += v * v;
    }
    for (int o = 16; o; o >>= 1) {
        s += __shfl_xor_sync(~0u, s, o);
        s2 += __shfl_xor_sync(~0u, s2, o);
    }
    int lane = threadIdx.x & 31, wid = threadIdx.x >> 5;
    if (lane == 0) { red0[wid] = s; red1[wid] = s2; }
    __syncthreads();
    if (wid == 0) {
        s = (lane < 8) ? red0[lane] : 0.f;
        s2 = (lane < 8) ? red1[lane] : 0.f;
        for (int o = 4; o; o >>= 1) {
            s += __shfl_xor_sync(~0u, s, o);
            s2 += __shfl_xor_sync(~0u, s2, o);
        }
        if (lane == 0) { red0[0] = s; red1[0] = s2; }
    }
    __syncthreads();
    float m = red0[0] * (1.f / DD);
    float var = red1[0] * (1.f / DD) - m * m;
    float inv = rsqrtf(var + 1e-5f);
    for (int i = threadIdx.x; i < DD; i += 256) {
        out[(size_t)row * DD + i] = (xr[i] - m) * inv * w[i] + b[i];
    }
}

// ---------------- GEMM v3: C_part[z] = A[64, kchunk] @ W[kchunk, 256-tile] ----------
// grid: (N/256, 1, SPLITK); block 256. Thread: 8 rows x 8 cols via f32x2.
// A staged once (k-major), W double-buffered 16-k tiles.
__global__ __launch_bounds__(256) void gemm_v3(const float* __restrict__ A,
                                               const float* __restrict__ W,
                                               float* __restrict__ part,
                                               int K, int N, int kchunk) {
    extern __shared__ float sm[];
    float* As = sm;                           // [kchunk][64]
    float* Ws = sm + kchunk * 64;             // [2][16][256]
    int n0 = blockIdx.x * 256;
    int z = blockIdx.z;
    int k0 = z * kchunk;
    int tid = threadIdx.x;
    int cg = tid & 31;            // column group: cols n0+cg*4.. and n0+128+cg*4..
    int rg = tid >> 5;            // row group: rows rg*8..rg*8+7

    // ---- stage A chunk (transpose to k-major) ----
    int kq = kchunk >> 2;
    int nf4 = 16 * kchunk;        // (64*kchunk)/4
    for (int idx = tid; idx < nf4; idx += 256) {
        int r = idx / kq;
        int c4 = (idx - r * kq) * 4;
        float4 av = *(const float4*)(A + (size_t)r * K + k0 + c4);
        As[(c4 + 0) * 64 + r] = av.x;
        As[(c4 + 1) * 64 + r] = av.y;
        As[(c4 + 2) * 64 + r] = av.z;
        As[(c4 + 3) * 64 + r] = av.w;
    }

    // ---- W tile prefetch helpers (16 k-rows x 256 cols = 1024 f4; 4 per thread) ----
    int wrow[4], wc4[4];
#pragma unroll
    for (int p = 0; p < 4; p++) {
        int idx = tid + p * 256;
        wrow[p] = idx >> 6;
        wc4[p] = (idx & 63) * 4;
    }
    float4 wreg[4];
#pragma unroll
    for (int p = 0; p < 4; p++)
        wreg[p] = *(const float4*)(W + (size_t)(k0 + wrow[p]) * N + n0 + wc4[p]);
#pragma unroll
    for (int p = 0; p < 4; p++)
        *(float4*)&Ws[wrow[p] * 256 + wc4[p]] = wreg[p];
    __syncthreads();

    int nt = kchunk >> 4;
    unsigned long long acc[4][8];
#pragma unroll
    for (int p = 0; p < 4; p++)
#pragma unroll
        for (int j = 0; j < 8; j++) acc[p][j] = 0ull;

    for (int t = 0; t < nt; t++) {
        if (t + 1 < nt) {
            int kk = k0 + (t + 1) * 16;
#pragma unroll
            for (int p = 0; p < 4; p++)
                wreg[p] = *(const float4*)(W + (size_t)(kk + wrow[p]) * N + n0 + wc4[p]);
        }
        const float* wb = &Ws[(t & 1) * 4096];
        const float* ab = &As[t * 16 * 64];
#pragma unroll
        for (int kk2 = 0; kk2 < 16; kk2++) {
            float4 w0 = *(const float4*)&wb[kk2 * 256 + cg * 4];
            float4 w1 = *(const float4*)&wb[kk2 * 256 + 128 + cg * 4];
            unsigned long long wp[8];
            wp[0] = pk2(w0.x, w0.x); wp[1] = pk2(w0.y, w0.y);
            wp[2] = pk2(w0.z, w0.z); wp[3] = pk2(w0.w, w0.w);
            wp[4] = pk2(w1.x, w1.x); wp[5] = pk2(w1.y, w1.y);
            wp[6] = pk2(w1.z, w1.z); wp[7] = pk2(w1.w, w1.w);
            F4U2 a01, a23;
            a01.f = *(const float4*)&ab[kk2 * 64 + rg * 8];
            a23.f = *(const float4*)&ab[kk2 * 64 + rg * 8 + 4];
#pragma unroll
            for (int j = 0; j < 8; j++) {
                fma2(acc[0][j], a01.u[0], wp[j]);
                fma2(acc[1][j], a01.u[1], wp[j]);
                fma2(acc[2][j], a23.u[0], wp[j]);
                fma2(acc[3][j], a23.u[1], wp[j]);
            }
        }
        if (t + 1 < nt) {
            int buf = (t + 1) & 1;
#pragma unroll
            for (int p = 0; p < 4; p++)
                *(float4*)&Ws[buf * 4096 + wrow[p] * 256 + wc4[p]] = wreg[p];
            __syncthreads();
        }
    }

    // ---- write partials ----
    float* po = part + (size_t)z * MM * N;
#pragma unroll
    for (int p = 0; p < 4; p++) {
        int r0 = rg * 8 + 2 * p;
        U2F2 u;
        float4 lo0, hi0, lo1, hi1;
        u.u = acc[p][0]; lo0.x = u.f.x; hi0.x = u.f.y;
        u.u = acc[p][1]; lo0.y = u.f.x; hi0.y = u.f.y;
        u.u = acc[p][2]; lo0.z = u.f.x; hi0.z = u.f.y;
        u.u = acc[p][3]; lo0.w = u.f.x; hi0.w = u.f.y;
        u.u = acc[p][4]; lo1.x = u.f.x; hi1.x = u.f.y;
        u.u = acc[p][5]; lo1.y = u.f.x; hi1.y = u.f.y;
        u.u = acc[p][6]; lo1.z = u.f.x; hi1.z = u.f.y;
        u.u = acc[p][7]; lo1.w = u.f.x; hi1.w = u.f.y;
        *(float4*)&po[(size_t)r0 * N + n0 + cg * 4] = lo0;
        *(float4*)&po[(size_t)r0 * N + n0 + 128 + cg * 4] = lo1;
        *(float4*)&po[(size_t)(r0 + 1) * N + n0 + cg * 4] = hi0;
        *(float4*)&po[(size_t)(r0 + 1) * N + n0 + 128 + cg * 4] = hi1;
    }
}

// ---------------- reduce partials + epilogue ----------------
__global__ __launch_bounds__(256) void reduce_epi(const float* __restrict__ part, int nz,
                                                  int MN, int N,
                                                  const float* __restrict__ bias,
                                                  const float* __restrict__ res,
                                                  float* __restrict__ out, int dogelu) {
    int i = blockIdx.x * 256 + threadIdx.x;
    if (i >= MN) return;
    float s = 0.f;
    for (int z = 0; z < nz; z++) s += part[(size_t)z * MN + i];
    if (bias) s += bias[i % N];
    if (dogelu) s = 0.5f * s * (1.f + erff(s * 0.70710678118654752440f));
    if (res) s += res[i];
    out[i] = s;
}

// ---------------- attention split kernel (flash-style partials) ----------------
#define SCP 380

__global__ __launch_bounds__(256) void attn_split(const float* __restrict__ q,
                                                  const float* __restrict__ kc,
                                                  const float* __restrict__ vc,
                                                  const float* __restrict__ kn,
                                                  const float* __restrict__ vn,
                                                  const float* __restrict__ mask,
                                                  float* __restrict__ apacc,
                                                  float* __restrict__ aml,
                                                  int Tk, int Tc, int chunk) {
    __shared__ float sc[8 * SCP];
    __shared__ float kt[32 * 68];
    __shared__ float qs[8 * 68];
    __shared__ float ml[16];

    int h = blockIdx.x, b = blockIdx.y, z = blockIdx.z;
    int k0 = z * chunk;
    int nv = min(Tk, k0 + chunk) - k0;
    int tid = threadIdx.x, lane = tid & 31, w = tid >> 5;

    // stage q (scaled by DH^-0.5 = 0.125 combined)
    if (tid < 128) {
        int qi = tid >> 4, d4 = (tid & 15) * 4;
        float4 v = *(const float4*)(q + (size_t)(b * TQ + qi) * DD + h * DH + d4);
        v.x *= 0.125f; v.y *= 0.125f; v.z *= 0.125f; v.w *= 0.125f;
        *(float4*)&qs[qi * 68 + d4] = v;
    }
    __syncthreads();

    int qrow = lane >> 2, kslot = lane & 3;
    int krow = w * 4 + kslot;

    // ---- pass 1: scores ----
    for (int kb = 0; kb < nv; kb += 32) {
        int nk = min(32, nv - kb);
        for (int i = tid; i < 512; i += 256) {   // 32 keys x 16 f4
            int key = i >> 4, d4 = (i & 15) * 4;
            if (key < nk) {
                int kg = k0 + kb + key;
                const float* src = (kg < Tc)
                    ? kc + ((size_t)b * Tc + kg) * DD + h * DH
                    : kn + (size_t)(b * TQ + (kg - Tc)) * DD + h * DH;
                *(float4*)&kt[key * 68 + d4] = *(const float4*)(src + d4);
            }
        }
        __syncthreads();
        if (krow < nk) {
            const float* qp = &qs[qrow * 68];
            const float* kp = &kt[krow * 68];
            float acc = 0.f;
#pragma unroll
            for (int d = 0; d < 64; d += 4) {
                float4 qv = *(const float4*)(qp + d);
                float4 kv = *(const float4*)(kp + d);
                acc += qv.x * kv.x + qv.y * kv.y + qv.z * kv.z + qv.w * kv.w;
            }
            if (mask) acc += mask[(size_t)qrow * Tk + k0 + kb + krow];
            sc[qrow * SCP + kb + krow] = acc;
        }
        __syncthreads();
    }

    // ---- partial softmax: warp w owns q row w ----
    {
        float m = -1e30f;
        for (int k = lane; k < nv; k += 32) m = fmaxf(m, sc[w * SCP + k]);
        for (int o = 16; o; o >>= 1) m = fmaxf(m, __shfl_xor_sync(~0u, m, o));
        float l = 0.f;
        for (int k = lane; k < nv; k += 32) {
            float e = __expf(sc[w * SCP + k] - m);
            sc[w * SCP + k] = e;
            l += e;
        }
        for (int o = 16; o; o >>= 1) l += __shfl_xor_sync(~0u, l, o);
        if (lane == 0) { ml[w * 2] = m; ml[w * 2 + 1] = l; }
    }

    // ---- pass 2: AV (warp w = q row w; lane owns dims 2l, 2l+1) ----
    float a0 = 0.f, a1 = 0.f;
    for (int kb = 0; kb < nv; kb += 32) {
        int nk = min(32, nv - kb);
        __syncthreads();   // previous kt use done
        for (int i = tid; i < 512; i += 256) {
            int key = i >> 4, d4 = (i & 15) * 4;
            if (key < nk) {
                int kg = k0 + kb + key;
                const float* src = (kg < Tc)
                    ? vc + ((size_t)b * Tc + kg) * DD + h * DH
                    : vn + (size_t)(b * TQ + (kg - Tc)) * DD + h * DH;
                *(float4*)&kt[key * 68 + d4] = *(const float4*)(src + d4);
            }
        }
        __syncthreads();
#pragma unroll 4
        for (int k = 0; k < nk; k++) {
            float p = sc[w * SCP + kb + k];
            float2 v2 = *(const float2*)&kt[k * 68 + 2 * lane];
            a0 += p * v2.x;
            a1 += p * v2.y;
        }
    }

    size_t idx = ((size_t)z * BB + b) * HH + h;
    float* ap = apacc + idx * TQ * DH;
    *(float2*)&ap[w * 64 + 2 * lane] = make_float2(a0, a1);
    if (tid < 16) aml[idx * 16 + tid] = ml[tid];
}

// ---------------- attention combine ----------------
__global__ __launch_bounds__(256) void attn_combine(const float* __restrict__ apacc,
                                                    const float* __restrict__ aml,
                                                    float* __restrict__ out, int S) {
    int h = blockIdx.x, b = blockIdx.y;
    int tid = threadIdx.x;
    int qi = tid >> 5, dp = tid & 31;
    float mstar = -1e30f;
    for (int z = 0; z < S; z++) {
        size_t idx = ((size_t)z * BB + b) * HH + h;
        mstar = fmaxf(mstar, aml[idx * 16 + qi * 2]);
    }
    float den = 0.f, n0 = 0.f, n1 = 0.f;
    for (int z = 0; z < S; z++) {
        size_t idx = ((size_t)z * BB + b) * HH + h;
        float mz = aml[idx * 16 + qi * 2];
        float lz = aml[idx * 16 + qi * 2 + 1];
        float s = __expf(mz - mstar);
        den += lz * s;
        float2 a = *(const float2*)&apacc[idx * TQ * DH + qi * 64 + dp * 2];
        n0 += a.x * s;
        n1 += a.y * s;
    }
    float inv = 1.f / den;
    float* o = out + (size_t)(b * TQ + qi) * DD + h * DH + dp * 2;
    o[0] = n0 * inv;
    o[1] = n1 * inv;
}

// ---------------- host orchestration ----------------
extern "C" void kernel_launch(void* const* d_in, const int* in_sizes, int n_in,
                              void* d_out, int out_size) {
    const float* x            = (const float*)d_in[0];
    const float* self_k_cache = (const float*)d_in[1];
    const float* self_v_cache = (const float*)d_in[2];
    const float* cross_k      = (const float*)d_in[3];
    const float* cross_v      = (const float*)d_in[4];
    const float* mask         = (const float*)d_in[5];
    const float* attn_wq = (const float*)d_in[6];
    const float* attn_bq = (const float*)d_in[7];
    const float* attn_wk = (const float*)d_in[8];
    const float* attn_wv = (const float*)d_in[9];
    const float* attn_bv = (const float*)d_in[10];
    const float* attn_wo = (const float*)d_in[11];
    const float* attn_bo = (const float*)d_in[12];
    const float* cross_wq = (const float*)d_in[13];
    const float* cross_bq = (const float*)d_in[14];
    const float* cross_wo = (const float*)d_in[15];
    const float* cross_bo = (const float*)d_in[16];
    const float* attn_ln_w = (const float*)d_in[17];
    const float* attn_ln_b = (const float*)d_in[18];
    const float* cross_ln_w = (const float*)d_in[19];
    const float* cross_ln_b = (const float*)d_in[20];
    const float* mlp_ln_w = (const float*)d_in[21];
    const float* mlp_ln_b = (const float*)d_in[22];
    const float* mlp_w1 = (const float*)d_in[23];
    const float* mlp_b1 = (const float*)d_in[24];
    const float* mlp_w2 = (const float*)d_in[25];
    const float* mlp_b2 = (const float*)d_in[26];

    float* out_x  = (float*)d_out;
    float* out_k1 = out_x + MM * DD;
    float* out_v1 = out_k1 + MM * DD;

    float *g_xl, *g_q, *g_attn, *g_x1, *g_h, *g_part, *g_apacc, *g_aml;
    cudaGetSymbolAddress((void**)&g_xl, g_xl_);
    cudaGetSymbolAddress((void**)&g_q, g_q_);
    cudaGetSymbolAddress((void**)&g_attn, g_attn_);
    cudaGetSymbolAddress((void**)&g_x1, g_x1_);
    cudaGetSymbolAddress((void**)&g_h, g_h_);
    cudaGetSymbolAddress((void**)&g_part, g_part_);
    cudaGetSymbolAddress((void**)&g_apacc, g_apacc_);
    cudaGetSymbolAddress((void**)&g_aml, g_aml_);

    // smem opt-in for the MLP GEMM config (80*64*4 + 32KB = 52 KB)
    static int smem_set = 0;
    if (!smem_set) {
        cudaFuncSetAttribute(gemm_v3, cudaFuncAttributeMaxDynamicSharedMemorySize, 53248);
        smem_set = 1;
    }

    const int MN_D = MM * DD;        // 81920
    const int MN_F = MM * DFF;       // 327680
    dim3 blk(256);

    // GEMM configs
    dim3 gD(DD / 256, 1, 20);   int kcD = 64;   int smD = kcD * 64 * 4 + 32768;  // 48 KB
    dim3 gF1(DFF / 256, 1, 16); int kcF1 = 80;  int smF = 80 * 64 * 4 + 32768;   // 52 KB
    dim3 gF2(DD / 256, 1, 64);  int kcF2 = 80;
    int redD = (MN_D + 255) / 256;
    int redF = (MN_F + 255) / 256;

    // attention configs
    int S_SELF = 2, CH_SELF = (TK_SELF + S_SELF - 1) / S_SELF;   // 228
    int S_CROSS = 4, CH_CROSS = (TC + S_CROSS - 1) / S_CROSS;    // 375

    // --- self-attention block ---
    ln_kernel<<<MM, blk>>>(x, attn_ln_w, attn_ln_b, g_xl);

    gemm_v3<<<gD, blk, smD>>>(g_xl, attn_wq, g_part, DD, DD, kcD);
    reduce_epi<<<redD, blk>>>(g_part, 20, MN_D, DD, attn_bq, nullptr, g_q, 0);

    gemm_v3<<<gD, blk, smD>>>(g_xl, attn_wk, g_part, DD, DD, kcD);
    reduce_epi<<<redD, blk>>>(g_part, 20, MN_D, DD, nullptr, nullptr, out_k1, 0);

    gemm_v3<<<gD, blk, smD>>>(g_xl, attn_wv, g_part, DD, DD, kcD);
    reduce_epi<<<redD, blk>>>(g_part, 20, MN_D, DD, attn_bv, nullptr, out_v1, 0);

    attn_split<<<dim3(HH, BB, S_SELF), blk>>>(g_q, self_k_cache, self_v_cache,
                                              out_k1, out_v1, mask,
                                              g_apacc, g_aml, TK_SELF, TP, CH_SELF);
    attn_combine<<<dim3(HH, BB), blk>>>(g_apacc, g_aml, g_attn, S_SELF);

    gemm_v3<<<gD, blk, smD>>>(g_attn, attn_wo, g_part, DD, DD, kcD);
    reduce_epi<<<redD, blk>>>(g_part, 20, MN_D, DD, attn_bo, x, g_x1, 0);

    // --- cross-attention block ---
    ln_kernel<<<MM, blk>>>(g_x1, cross_ln_w, cross_ln_b, g_xl);

    gemm_v3<<<gD, blk, smD>>>(g_xl, cross_wq, g_part, DD, DD, kcD);
    reduce_epi<<<redD, blk>>>(g_part, 20, MN_D, DD, cross_bq, nullptr, g_q, 0);

    attn_split<<<dim3(HH, BB, S_CROSS), blk>>>(g_q, cross_k, cross_v,
                                               nullptr, nullptr, nullptr,
                                               g_apacc, g_aml, TC, TC, CH_CROSS);
    attn_combine<<<dim3(HH, BB), blk>>>(g_apacc, g_aml, g_attn, S_CROSS);

    gemm_v3<<<gD, blk, smD>>>(g_attn, cross_wo, g_part, DD, DD, kcD);
    reduce_epi<<<redD, blk>>>(g_part, 20, MN_D, DD, cross_bo, g_x1, out_x, 0);

    // --- MLP block ---
    ln_kernel<<<MM, blk>>>(out_x, mlp_ln_w, mlp_ln_b, g_xl);

    gemm_v3<<<gF1, blk, smF>>>(g_xl, mlp_w1, g_part, DD, DFF, kcF1);
    reduce_epi<<<redF, blk>>>(g_part, 16, MN_F, DFF, mlp_b1, nullptr, g_h, 1);

    gemm_v3<<<gF2, blk, smF>>>(g_h, mlp_w2, g_part, DFF, DD, kcF2);
    reduce_epi<<<redD, blk>>>(g_part, 64, MN_D, DD, mlp_b2, out_x, out_x, 0);
}

// round 6
// speedup vs baseline: 1.7364x; 1.3166x over previous
#include <cuda_runtime.h>
#include <cuda_bf16.h>
#include <cstdint>
#include <math.h>

// ---------------- problem constants ----------------
#define BB 8
#define TQ 8
#define TP 447
#define TC 1500
#define DD 1280
#define HH 20
#define DH 64
#define DFF 5120
#define MM 64              // B*TQ rows
#define TK_SELF (TP + TQ)  // 455

// ---------------- scratch (device globals; no allocation allowed) ----------------
__device__ float g_xl_[MM * DD];
__device__ float g_q_[MM * DD];
__device__ float g_attn_[MM * DD];
__device__ float g_x1_[MM * DD];
__device__ float g_h_[MM * DFF];
__device__ float g_part_[1310720];                  // split-K partials (max 8x64x1280 / 2x64x5120)
__device__ float g_apacc_[16 * BB * HH * TQ * DH];  // attn split partial acc
__device__ float g_aml_[16 * BB * HH * 16];         // attn split (m,l) per q

// ---------------- helpers ----------------
__device__ __forceinline__ uint32_t smem_to_u32(const void* p) {
    uint32_t a;
    asm("{ .reg .u64 t; cvta.to.shared.u64 t, %1; cvt.u32.u64 %0, t; }" : "=r"(a) : "l"(p));
    return a;
}
__device__ __forceinline__ uint32_t f2tf(float f) {
    uint32_t r;
    asm("cvt.rna.tf32.f32 %0, %1;" : "=r"(r) : "f"(f));
    return r;
}
#define LDMX4(r0, r1, r2, r3, addr) \
    asm volatile("ldmatrix.sync.aligned.m8n8.x4.shared.b16 {%0,%1,%2,%3}, [%4];" \
                 : "=r"(r0), "=r"(r1), "=r"(r2), "=r"(r3) : "r"(addr))
__device__ __forceinline__ void mma_tf32(float c[4], uint32_t a0, uint32_t a1,
                                         uint32_t a2, uint32_t a3,
                                         uint32_t b0, uint32_t b1) {
    asm volatile(
        "mma.sync.aligned.m16n8k8.row.col.f32.tf32.tf32.f32 "
        "{%0,%1,%2,%3}, {%4,%5,%6,%7}, {%8,%9}, {%0,%1,%2,%3};"
        : "+f"(c[0]), "+f"(c[1]), "+f"(c[2]), "+f"(c[3])
        : "r"(a0), "r"(a1), "r"(a2), "r"(a3), "r"(b0), "r"(b1));
}

// ---------------- LayerNorm: one block per row ----------------
__global__ __launch_bounds__(256) void ln_kernel(const float* __restrict__ x,
                                                 const float* __restrict__ w,
                                                 const float* __restrict__ b,
                                                 float* __restrict__ out) {
    int row = blockIdx.x;
    const float* xr = x + (size_t)row * DD;
    __shared__ float red0[32], red1[32];
    float s = 0.f, s2 = 0.f;
    for (int i = threadIdx.x; i < DD; i += 256) {
        float v = xr[i];
        s += v;
        s2 += v * v;
    }
    for (int o = 16; o; o >>= 1) {
        s += __shfl_xor_sync(~0u, s, o);
        s2 += __shfl_xor_sync(~0u, s2, o);
    }
    int lane = threadIdx.x & 31, wid = threadIdx.x >> 5;
    if (lane == 0) { red0[wid] = s; red1[wid] = s2; }
    __syncthreads();
    if (wid == 0) {
        s = (lane < 8) ? red0[lane] : 0.f;
        s2 = (lane < 8) ? red1[lane] : 0.f;
        for (int o = 4; o; o >>= 1) {
            s += __shfl_xor_sync(~0u, s, o);
            s2 += __shfl_xor_sync(~0u, s2, o);
        }
        if (lane == 0) { red0[0] = s; red1[0] = s2; }
    }
    __syncthreads();
    float m = red0[0] * (1.f / DD);
    float var = red1[0] * (1.f / DD) - m * m;
    float inv = rsqrtf(var + 1e-5f);
    for (int i = threadIdx.x; i < DD; i += 256) {
        out[(size_t)row * DD + i] = (xr[i] - m) * inv * w[i] + b[i];
    }
}

// ---------------- mma.sync tf32 split-K GEMM ----------------
// C_part[z][64, n0:n0+64] = A[64, k0:k0+kc] @ W[k0:k0+kc, n0:n0+64]
// 8 warps: 4 in M (m16 each) x 2 in N (32 cols each). K staged 32/stage,
// double-buffered with LDG prefetch into registers during the MMA loop.
#define SA 36   // smem row stride in floats (144B, 16B-aligned)

__global__ __launch_bounds__(256) void gemm_mma(const float* __restrict__ A,
                                                const float* __restrict__ W,
                                                float* __restrict__ part,
                                                int K, int N, int kc) {
    __shared__ __align__(16) uint32_t As[2][64 * SA];
    __shared__ __align__(16) uint32_t Bs[2][64 * SA];
    int tid = threadIdx.x, lane = tid & 31, w = tid >> 5;
    int wm = w & 3, wn = w >> 2;
    int n0 = blockIdx.x * 64;
    int z = blockIdx.z, k0 = z * kc;
    int nst = kc >> 5;

    // ldmatrix source lanes
    int a_row = wm * 16 + ((lane >> 3) & 1) * 8 + (lane & 7);
    uint32_t a_koff = ((lane >> 4) & 1) * 16;
    int b_row_off = ((lane >> 4) & 1) * 8 + (lane & 7);
    uint32_t b_koff = ((lane >> 3) & 1) * 16;
    uint32_t aAddr0 = smem_to_u32(&As[0][0]) + (uint32_t)(a_row * SA) * 4 + a_koff;
    uint32_t bAddr0 = smem_to_u32(&Bs[0][0]) + b_koff;

    // staging indices
    int s_row = tid >> 2, s_c4 = tid & 3;         // A: 2 float4 per thread (c4 and c4+4)
    int s_n = tid & 63, s_k = tid >> 6;           // B: 8 scalars per thread

    float c[4][4];
#pragma unroll
    for (int j = 0; j < 4; j++)
#pragma unroll
        for (int i = 0; i < 4; i++) c[j][i] = 0.f;

    // ---- prologue: stage 0 ----
    {
        const float* ar = A + (size_t)s_row * K + k0;
        float4 v0 = *(const float4*)(ar + s_c4 * 4);
        float4 v1 = *(const float4*)(ar + (s_c4 + 4) * 4);
        uint4 u0 = make_uint4(f2tf(v0.x), f2tf(v0.y), f2tf(v0.z), f2tf(v0.w));
        uint4 u1 = make_uint4(f2tf(v1.x), f2tf(v1.y), f2tf(v1.z), f2tf(v1.w));
        *(uint4*)&As[0][s_row * SA + s_c4 * 4] = u0;
        *(uint4*)&As[0][s_row * SA + (s_c4 + 4) * 4] = u1;
        const float* wp = W + (size_t)k0 * N + n0 + s_n;
#pragma unroll
        for (int j = 0; j < 8; j++) {
            int k2 = s_k + j * 4;
            Bs[0][s_n * SA + k2] = f2tf(wp[(size_t)k2 * N]);
        }
    }
    __syncthreads();

    for (int st = 0; st < nst; st++) {
        int buf = st & 1;
        // prefetch next stage into registers
        float4 pa0, pa1;
        float pb[8];
        if (st + 1 < nst) {
            int kb = k0 + (st + 1) * 32;
            const float* ar = A + (size_t)s_row * K + kb;
            pa0 = *(const float4*)(ar + s_c4 * 4);
            pa1 = *(const float4*)(ar + (s_c4 + 4) * 4);
            const float* wp = W + (size_t)kb * N + n0 + s_n;
#pragma unroll
            for (int j = 0; j < 8; j++) pb[j] = wp[(size_t)(s_k + j * 4) * N];
        }
        // compute on current buffer
        uint32_t aB = aAddr0 + (uint32_t)buf * 64 * SA * 4;
#pragma unroll
        for (int s = 0; s < 4; s++) {
            uint32_t a0, a1, a2, a3;
            LDMX4(a0, a1, a2, a3, aB + s * 32);
#pragma unroll
            for (int jp = 0; jp < 2; jp++) {
                uint32_t b0, b1, b2, b3;
                uint32_t baddr = bAddr0 + (uint32_t)buf * 64 * SA * 4 +
                                 (uint32_t)((wn * 32 + jp * 16 + b_row_off) * SA) * 4 + s * 32;
                LDMX4(b0, b1, b2, b3, baddr);
                mma_tf32(c[jp * 2], a0, a1, a2, a3, b0, b1);
                mma_tf32(c[jp * 2 + 1], a0, a1, a2, a3, b2, b3);
            }
        }
        // store prefetched stage into the other buffer
        if (st + 1 < nst) {
            int nb = buf ^ 1;
            uint4 u0 = make_uint4(f2tf(pa0.x), f2tf(pa0.y), f2tf(pa0.z), f2tf(pa0.w));
            uint4 u1 = make_uint4(f2tf(pa1.x), f2tf(pa1.y), f2tf(pa1.z), f2tf(pa1.w));
            *(uint4*)&As[nb][s_row * SA + s_c4 * 4] = u0;
            *(uint4*)&As[nb][s_row * SA + (s_c4 + 4) * 4] = u1;
#pragma unroll
            for (int j = 0; j < 8; j++)
                Bs[nb][s_n * SA + s_k + j * 4] = f2tf(pb[j]);
            __syncthreads();
        }
    }

    // ---- epilogue: write partials ----
    int g = lane >> 2, t = lane & 3;
    float* po = part + (size_t)z * MM * N;
#pragma unroll
    for (int j = 0; j < 4; j++) {
        int col = n0 + wn * 32 + j * 8 + 2 * t;
        int r0 = wm * 16 + g;
        *(float2*)&po[(size_t)r0 * N + col] = make_float2(c[j][0], c[j][1]);
        *(float2*)&po[(size_t)(r0 + 8) * N + col] = make_float2(c[j][2], c[j][3]);
    }
}

// ---------------- reduce partials + epilogue ----------------
__global__ __launch_bounds__(256) void reduce_epi(const float* __restrict__ part, int nz,
                                                  int MN, int N,
                                                  const float* __restrict__ bias,
                                                  const float* __restrict__ res,
                                                  float* __restrict__ out, int dogelu) {
    int i = blockIdx.x * 256 + threadIdx.x;
    if (i >= MN) return;
    float s = 0.f;
    for (int z = 0; z < nz; z++) s += part[(size_t)z * MN + i];
    if (bias) s += bias[i % N];
    if (dogelu) s = 0.5f * s * (1.f + erff(s * 0.70710678118654752440f));
    if (res) s += res[i];
    out[i] = s;
}

// ---------------- attention split kernel (flash-style partials) ----------------
#define SCP 380

__global__ __launch_bounds__(256) void attn_split(const float* __restrict__ q,
                                                  const float* __restrict__ kc,
                                                  const float* __restrict__ vc,
                                                  const float* __restrict__ kn,
                                                  const float* __restrict__ vn,
                                                  const float* __restrict__ mask,
                                                  float* __restrict__ apacc,
                                                  float* __restrict__ aml,
                                                  int Tk, int Tc, int chunk) {
    __shared__ float sc[8 * SCP];
    __shared__ float kt[32 * 68];
    __shared__ float qs[8 * 68];
    __shared__ float ml[16];

    int h = blockIdx.x, b = blockIdx.y, z = blockIdx.z;
    int k0 = z * chunk;
    int nv = min(Tk, k0 + chunk) - k0;
    int tid = threadIdx.x, lane = tid & 31, w = tid >> 5;

    if (tid < 128) {
        int qi = tid >> 4, d4 = (tid & 15) * 4;
        float4 v = *(const float4*)(q + (size_t)(b * TQ + qi) * DD + h * DH + d4);
        v.x *= 0.125f; v.y *= 0.125f; v.z *= 0.125f; v.w *= 0.125f;
        *(float4*)&qs[qi * 68 + d4] = v;
    }
    __syncthreads();

    int qrow = lane >> 2, kslot = lane & 3;
    int krow = w * 4 + kslot;

    for (int kb = 0; kb < nv; kb += 32) {
        int nk = min(32, nv - kb);
        for (int i = tid; i < 512; i += 256) {
            int key = i >> 4, d4 = (i & 15) * 4;
            if (key < nk) {
                int kg = k0 + kb + key;
                const float* src = (kg < Tc)
                    ? kc + ((size_t)b * Tc + kg) * DD + h * DH
                    : kn + (size_t)(b * TQ + (kg - Tc)) * DD + h * DH;
                *(float4*)&kt[key * 68 + d4] = *(const float4*)(src + d4);
            }
        }
        __syncthreads();
        if (krow < nk) {
            const float* qp = &qs[qrow * 68];
            const float* kp = &kt[krow * 68];
            float acc = 0.f;
#pragma unroll
            for (int d = 0; d < 64; d += 4) {
                float4 qv = *(const float4*)(qp + d);
                float4 kv = *(const float4*)(kp + d);
                acc += qv.x * kv.x + qv.y * kv.y + qv.z * kv.z + qv.w * kv.w;
            }
            if (mask) acc += mask[(size_t)qrow * Tk + k0 + kb + krow];
            sc[qrow * SCP + kb + krow] = acc;
        }
        __syncthreads();
    }

    {
        float m = -1e30f;
        for (int k = lane; k < nv; k += 32) m = fmaxf(m, sc[w * SCP + k]);
        for (int o = 16; o; o >>= 1) m = fmaxf(m, __shfl_xor_sync(~0u, m, o));
        float l = 0.f;
        for (int k = lane; k < nv; k += 32) {
            float e = __expf(sc[w * SCP + k] - m);
            sc[w * SCP + k] = e;
            l += e;
        }
        for (int o = 16; o; o >>= 1) l += __shfl_xor_sync(~0u, l, o);
        if (lane == 0) { ml[w * 2] = m; ml[w * 2 + 1] = l; }
    }

    float a0 = 0.f, a1 = 0.f;
    for (int kb = 0; kb < nv; kb += 32) {
        int nk = min(32, nv - kb);
        __syncthreads();
        for (int i = tid; i < 512; i += 256) {
            int key = i >> 4, d4 = (i & 15) * 4;
            if (key < nk) {
                int kg = k0 + kb + key;
                const float* src = (kg < Tc)
                    ? vc + ((size_t)b * Tc + kg) * DD + h * DH
                    : vn + (size_t)(b * TQ + (kg - Tc)) * DD + h * DH;
                *(float4*)&kt[key * 68 + d4] = *(const float4*)(src + d4);
            }
        }
        __syncthreads();
#pragma unroll 4
        for (int k = 0; k < nk; k++) {
            float p = sc[w * SCP + kb + k];
            float2 v2 = *(const float2*)&kt[k * 68 + 2 * lane];
            a0 += p * v2.x;
            a1 += p * v2.y;
        }
    }

    size_t idx = ((size_t)z * BB + b) * HH + h;
    float* ap = apacc + idx * TQ * DH;
    *(float2*)&ap[w * 64 + 2 * lane] = make_float2(a0, a1);
    if (tid < 16) aml[idx * 16 + tid] = ml[tid];
}

// ---------------- attention combine ----------------
__global__ __launch_bounds__(256) void attn_combine(const float* __restrict__ apacc,
                                                    const float* __restrict__ aml,
                                                    float* __restrict__ out, int S) {
    int h = blockIdx.x, b = blockIdx.y;
    int tid = threadIdx.x;
    int qi = tid >> 5, dp = tid & 31;
    float mstar = -1e30f;
    for (int z = 0; z < S; z++) {
        size_t idx = ((size_t)z * BB + b) * HH + h;
        mstar = fmaxf(mstar, aml[idx * 16 + qi * 2]);
    }
    float den = 0.f, n0 = 0.f, n1 = 0.f;
    for (int z = 0; z < S; z++) {
        size_t idx = ((size_t)z * BB + b) * HH + h;
        float mz = aml[idx * 16 + qi * 2];
        float lz = aml[idx * 16 + qi * 2 + 1];
        float s = __expf(mz - mstar);
        den += lz * s;
        float2 a = *(const float2*)&apacc[idx * TQ * DH + qi * 64 + dp * 2];
        n0 += a.x * s;
        n1 += a.y * s;
    }
    float inv = 1.f / den;
    float* o = out + (size_t)(b * TQ + qi) * DD + h * DH + dp * 2;
    o[0] = n0 * inv;
    o[1] = n1 * inv;
}

// ---------------- host orchestration ----------------
extern "C" void kernel_launch(void* const* d_in, const int* in_sizes, int n_in,
                              void* d_out, int out_size) {
    const float* x            = (const float*)d_in[0];
    const float* self_k_cache = (const float*)d_in[1];
    const float* self_v_cache = (const float*)d_in[2];
    const float* cross_k      = (const float*)d_in[3];
    const float* cross_v      = (const float*)d_in[4];
    const float* mask         = (const float*)d_in[5];
    const float* attn_wq = (const float*)d_in[6];
    const float* attn_bq = (const float*)d_in[7];
    const float* attn_wk = (const float*)d_in[8];
    const float* attn_wv = (const float*)d_in[9];
    const float* attn_bv = (const float*)d_in[10];
    const float* attn_wo = (const float*)d_in[11];
    const float* attn_bo = (const float*)d_in[12];
    const float* cross_wq = (const float*)d_in[13];
    const float* cross_bq = (const float*)d_in[14];
    const float* cross_wo = (const float*)d_in[15];
    const float* cross_bo = (const float*)d_in[16];
    const float* attn_ln_w = (const float*)d_in[17];
    const float* attn_ln_b = (const float*)d_in[18];
    const float* cross_ln_w = (const float*)d_in[19];
    const float* cross_ln_b = (const float*)d_in[20];
    const float* mlp_ln_w = (const float*)d_in[21];
    const float* mlp_ln_b = (const float*)d_in[22];
    const float* mlp_w1 = (const float*)d_in[23];
    const float* mlp_b1 = (const float*)d_in[24];
    const float* mlp_w2 = (const float*)d_in[25];
    const float* mlp_b2 = (const float*)d_in[26];

    float* out_x  = (float*)d_out;
    float* out_k1 = out_x + MM * DD;
    float* out_v1 = out_k1 + MM * DD;

    float *g_xl, *g_q, *g_attn, *g_x1, *g_h, *g_part, *g_apacc, *g_aml;
    cudaGetSymbolAddress((void**)&g_xl, g_xl_);
    cudaGetSymbolAddress((void**)&g_q, g_q_);
    cudaGetSymbolAddress((void**)&g_attn, g_attn_);
    cudaGetSymbolAddress((void**)&g_x1, g_x1_);
    cudaGetSymbolAddress((void**)&g_h, g_h_);
    cudaGetSymbolAddress((void**)&g_part, g_part_);
    cudaGetSymbolAddress((void**)&g_apacc, g_apacc_);
    cudaGetSymbolAddress((void**)&g_aml, g_aml_);

    const int MN_D = MM * DD;        // 81920
    const int MN_F = MM * DFF;       // 327680
    dim3 blk(256);

    // GEMM configs: N-tile 64, K-tile 32
    dim3 gD(DD / 64, 1, 8);      // D GEMM: kc=160 (5 stages), 160 CTAs
    dim3 gF1(DFF / 64, 1, 2);    // MLP1: kc=640 (20 stages), 160 CTAs
    dim3 gF2(DD / 64, 1, 8);     // MLP2: kc=640 (20 stages), 160 CTAs
    int redD = (MN_D + 255) / 256;
    int redF = (MN_F + 255) / 256;

    int S_SELF = 4, CH_SELF = (TK_SELF + S_SELF - 1) / S_SELF;   // 114
    int S_CROSS = 10, CH_CROSS = TC / S_CROSS;                   // 150

    // --- self-attention block ---
    ln_kernel<<<MM, blk>>>(x, attn_ln_w, attn_ln_b, g_xl);

    gemm_mma<<<gD, blk>>>(g_xl, attn_wq, g_part, DD, DD, 160);
    reduce_epi<<<redD, blk>>>(g_part, 8, MN_D, DD, attn_bq, nullptr, g_q, 0);

    gemm_mma<<<gD, blk>>>(g_xl, attn_wk, g_part, DD, DD, 160);
    reduce_epi<<<redD, blk>>>(g_part, 8, MN_D, DD, nullptr, nullptr, out_k1, 0);

    gemm_mma<<<gD, blk>>>(g_xl, attn_wv, g_part, DD, DD, 160);
    reduce_epi<<<redD, blk>>>(g_part, 8, MN_D, DD, attn_bv, nullptr, out_v1, 0);

    attn_split<<<dim3(HH, BB, S_SELF), blk>>>(g_q, self_k_cache, self_v_cache,
                                              out_k1, out_v1, mask,
                                              g_apacc, g_aml, TK_SELF, TP, CH_SELF);
    attn_combine<<<dim3(HH, BB), blk>>>(g_apacc, g_aml, g_attn, S_SELF);

    gemm_mma<<<gD, blk>>>(g_attn, attn_wo, g_part, DD, DD, 160);
    reduce_epi<<<redD, blk>>>(g_part, 8, MN_D, DD, attn_bo, x, g_x1, 0);

    // --- cross-attention block ---
    ln_kernel<<<MM, blk>>>(g_x1, cross_ln_w, cross_ln_b, g_xl);

    gemm_mma<<<gD, blk>>>(g_xl, cross_wq, g_part, DD, DD, 160);
    reduce_epi<<<redD, blk>>>(g_part, 8, MN_D, DD, cross_bq, nullptr, g_q, 0);

    attn_split<<<dim3(HH, BB, S_CROSS), blk>>>(g_q, cross_k, cross_v,
                                               nullptr, nullptr, nullptr,
                                               g_apacc, g_aml, TC, TC, CH_CROSS);
    attn_combine<<<dim3(HH, BB), blk>>>(g_apacc, g_aml, g_attn, S_CROSS);

    gemm_mma<<<gD, blk>>>(g_attn, cross_wo, g_part, DD, DD, 160);
    reduce_epi<<<redD, blk>>>(g_part, 8, MN_D, DD, cross_bo, g_x1, out_x, 0);

    // --- MLP block ---
    ln_kernel<<<MM, blk>>>(out_x, mlp_ln_w, mlp_ln_b, g_xl);

    gemm_mma<<<gF1, blk>>>(g_xl, mlp_w1, g_part, DD, DFF, 640);
    reduce_epi<<<redF, blk>>>(g_part, 2, MN_F, DFF, mlp_b1, nullptr, g_h, 1);

    gemm_mma<<<gF2, blk>>>(g_h, mlp_w2, g_part, DFF, DD, 640);
    reduce_epi<<<redD, blk>>>(g_part, 8, MN_D, DD, mlp_b2, out_x, out_x, 0);
}

// round 8
// speedup vs baseline: 1.9984x; 1.1509x over previous
#include <cuda_runtime.h>
#include <cuda_bf16.h>
#include <cstdint>
#include <math.h>

// ---------------- problem constants ----------------
#define BB 8
#define TQ 8
#define TP 447
#define TC 1500
#define DD 1280
#define HH 20
#define DH 64
#define DFF 5120
#define MM 64              // B*TQ rows
#define TK_SELF (TP + TQ)  // 455

// ---------------- scratch (device globals; no allocation allowed) ----------------
__device__ float g_xl_[MM * DD];
__device__ float g_q_[MM * DD];
__device__ float g_attn_[MM * DD];
__device__ float g_x1_[MM * DD];
__device__ float g_h_[MM * DFF];
__device__ float g_part_[4915200];                  // split-K partials (max 20x3x64x1280)
__device__ float g_apacc_[16 * BB * HH * TQ * DH];  // attn split partial acc
__device__ float g_aml_[16 * BB * HH * 16];         // attn split (m,l) per q

// ---------------- helpers ----------------
__device__ __forceinline__ uint32_t smem_to_u32(const void* p) {
    uint32_t a;
    asm("{ .reg .u64 t; cvta.to.shared.u64 t, %1; cvt.u32.u64 %0, t; }" : "=r"(a) : "l"(p));
    return a;
}
__device__ __forceinline__ uint32_t f2tf(float f) {
    uint32_t r;
    asm("cvt.rna.tf32.f32 %0, %1;" : "=r"(r) : "f"(f));
    return r;
}
#define LDMX4(r0, r1, r2, r3, addr) \
    asm volatile("ldmatrix.sync.aligned.m8n8.x4.shared.b16 {%0,%1,%2,%3}, [%4];" \
                 : "=r"(r0), "=r"(r1), "=r"(r2), "=r"(r3) : "r"(addr))
__device__ __forceinline__ void mma_tf32(float c[4], uint32_t a0, uint32_t a1,
                                         uint32_t a2, uint32_t a3,
                                         uint32_t b0, uint32_t b1) {
    asm volatile(
        "mma.sync.aligned.m16n8k8.row.col.f32.tf32.tf32.f32 "
        "{%0,%1,%2,%3}, {%4,%5,%6,%7}, {%8,%9}, {%0,%1,%2,%3};"
        : "+f"(c[0]), "+f"(c[1]), "+f"(c[2]), "+f"(c[3])
        : "r"(a0), "r"(a1), "r"(a2), "r"(a3), "r"(b0), "r"(b1));
}

// ---------------- LayerNorm: one block per row ----------------
__global__ __launch_bounds__(256) void ln_kernel(const float* __restrict__ x,
                                                 const float* __restrict__ w,
                                                 const float* __restrict__ b,
                                                 float* __restrict__ out) {
    int row = blockIdx.x;
    const float* xr = x + (size_t)row * DD;
    __shared__ float red0[32], red1[32];
    float s = 0.f, s2 = 0.f;
    for (int i = threadIdx.x; i < DD; i += 256) {
        float v = xr[i];
        s += v;
        s2 += v * v;
    }
    for (int o = 16; o; o >>= 1) {
        s += __shfl_xor_sync(~0u, s, o);
        s2 += __shfl_xor_sync(~0u, s2, o);
    }
    int lane = threadIdx.x & 31, wid = threadIdx.x >> 5;
    if (lane == 0) { red0[wid] = s; red1[wid] = s2; }
    __syncthreads();
    if (wid == 0) {
        s = (lane < 8) ? red0[lane] : 0.f;
        s2 = (lane < 8) ? red1[lane] : 0.f;
        for (int o = 4; o; o >>= 1) {
            s += __shfl_xor_sync(~0u, s, o);
            s2 += __shfl_xor_sync(~0u, s2, o);
        }
        if (lane == 0) { red0[0] = s; red1[0] = s2; }
    }
    __syncthreads();
    float m = red0[0] * (1.f / DD);
    float var = red1[0] * (1.f / DD) - m * m;
    float inv = rsqrtf(var + 1e-5f);
    for (int i = threadIdx.x; i < DD; i += 256) {
        out[(size_t)row * DD + i] = (xr[i] - m) * inv * w[i] + b[i];
    }
}

// ---------------- mma.sync tf32 split-K GEMM ----------------
// blockIdx.y selects weight slab (fused QKV); partials layout [z][slab][64][N].
// 8 warps: 4 in M (m16 each) x 2 in N (32 cols each). K staged 32/stage,
// double-buffered with LDG prefetch into registers during the MMA loop.
#define SA 36   // smem row stride in floats (144B, 16B-aligned)

__global__ __launch_bounds__(256) void gemm_mma(const float* __restrict__ A,
                                                const float* __restrict__ W0,
                                                const float* __restrict__ W1,
                                                const float* __restrict__ W2,
                                                float* __restrict__ part,
                                                int K, int N, int kc) {
    __shared__ __align__(16) uint32_t As[2][64 * SA];
    __shared__ __align__(16) uint32_t Bs[2][64 * SA];
    int tid = threadIdx.x, lane = tid & 31, w = tid >> 5;
    int wm = w & 3, wn = w >> 2;
    int n0 = blockIdx.x * 64;
    int slab = blockIdx.y;
    const float* W = (slab == 0) ? W0 : ((slab == 1) ? W1 : W2);
    int z = blockIdx.z, k0 = z * kc;
    int nst = kc >> 5;

    // ldmatrix source lanes
    int a_row = wm * 16 + ((lane >> 3) & 1) * 8 + (lane & 7);
    uint32_t a_koff = ((lane >> 4) & 1) * 16;
    int b_row_off = ((lane >> 4) & 1) * 8 + (lane & 7);
    uint32_t b_koff = ((lane >> 3) & 1) * 16;
    uint32_t aAddr0 = smem_to_u32(&As[0][0]) + (uint32_t)(a_row * SA) * 4 + a_koff;
    uint32_t bAddr0 = smem_to_u32(&Bs[0][0]) + b_koff;

    // staging indices
    int s_row = tid >> 2, s_c4 = tid & 3;         // A: 2 float4 per thread (c4 and c4+4)
    int s_n = tid & 63, s_k = tid >> 6;           // B: 8 scalars per thread

    float c[4][4];
#pragma unroll
    for (int j = 0; j < 4; j++)
#pragma unroll
        for (int i = 0; i < 4; i++) c[j][i] = 0.f;

    // ---- prologue: stage 0 ----
    {
        const float* ar = A + (size_t)s_row * K + k0;
        float4 v0 = *(const float4*)(ar + s_c4 * 4);
        float4 v1 = *(const float4*)(ar + (s_c4 + 4) * 4);
        uint4 u0 = make_uint4(f2tf(v0.x), f2tf(v0.y), f2tf(v0.z), f2tf(v0.w));
        uint4 u1 = make_uint4(f2tf(v1.x), f2tf(v1.y), f2tf(v1.z), f2tf(v1.w));
        *(uint4*)&As[0][s_row * SA + s_c4 * 4] = u0;
        *(uint4*)&As[0][s_row * SA + (s_c4 + 4) * 4] = u1;
        const float* wp = W + (size_t)k0 * N + n0 + s_n;
#pragma unroll
        for (int j = 0; j < 8; j++) {
            int k2 = s_k + j * 4;
            Bs[0][s_n * SA + k2] = f2tf(wp[(size_t)k2 * N]);
        }
    }
    __syncthreads();

    for (int st = 0; st < nst; st++) {
        int buf = st & 1;
        // prefetch next stage into registers
        float4 pa0, pa1;
        float pb[8];
        if (st + 1 < nst) {
            int kb = k0 + (st + 1) * 32;
            const float* ar = A + (size_t)s_row * K + kb;
            pa0 = *(const float4*)(ar + s_c4 * 4);
            pa1 = *(const float4*)(ar + (s_c4 + 4) * 4);
            const float* wp = W + (size_t)kb * N + n0 + s_n;
#pragma unroll
            for (int j = 0; j < 8; j++) pb[j] = wp[(size_t)(s_k + j * 4) * N];
        }
        // compute on current buffer
        uint32_t aB = aAddr0 + (uint32_t)buf * 64 * SA * 4;
#pragma unroll
        for (int s = 0; s < 4; s++) {
            uint32_t a0, a1, a2, a3;
            LDMX4(a0, a1, a2, a3, aB + s * 32);
#pragma unroll
            for (int jp = 0; jp < 2; jp++) {
                uint32_t b0, b1, b2, b3;
                uint32_t baddr = bAddr0 + (uint32_t)buf * 64 * SA * 4 +
                                 (uint32_t)((wn * 32 + jp * 16 + b_row_off) * SA) * 4 + s * 32;
                LDMX4(b0, b1, b2, b3, baddr);
                mma_tf32(c[jp * 2], a0, a1, a2, a3, b0, b1);
                mma_tf32(c[jp * 2 + 1], a0, a1, a2, a3, b2, b3);
            }
        }
        // store prefetched stage into the other buffer
        if (st + 1 < nst) {
            int nb = buf ^ 1;
            uint4 u0 = make_uint4(f2tf(pa0.x), f2tf(pa0.y), f2tf(pa0.z), f2tf(pa0.w));
            uint4 u1 = make_uint4(f2tf(pa1.x), f2tf(pa1.y), f2tf(pa1.z), f2tf(pa1.w));
            *(uint4*)&As[nb][s_row * SA + s_c4 * 4] = u0;
            *(uint4*)&As[nb][s_row * SA + (s_c4 + 4) * 4] = u1;
#pragma unroll
            for (int j = 0; j < 8; j++)
                Bs[nb][s_n * SA + s_k + j * 4] = f2tf(pb[j]);
            __syncthreads();
        }
    }

    // ---- epilogue: write partials ----
    int g = lane >> 2, t = lane & 3;
    float* po = part + ((size_t)z * gridDim.y + slab) * MM * N;
#pragma unroll
    for (int j = 0; j < 4; j++) {
        int col = n0 + wn * 32 + j * 8 + 2 * t;
        int r0 = wm * 16 + g;
        *(float2*)&po[(size_t)r0 * N + col] = make_float2(c[j][0], c[j][1]);
        *(float2*)&po[(size_t)(r0 + 8) * N + col] = make_float2(c[j][2], c[j][3]);
    }
}

// ---------------- reduce partials + epilogue (multi-slab) ----------------
// partials layout: [z][slab][MN]; blockIdx.y = slab.
__global__ __launch_bounds__(256) void reduce_epi(const float* __restrict__ part, int nz,
                                                  int MN, int N,
                                                  const float* __restrict__ b0,
                                                  const float* __restrict__ b1,
                                                  const float* __restrict__ b2,
                                                  const float* __restrict__ res,
                                                  float* __restrict__ o0,
                                                  float* __restrict__ o1,
                                                  float* __restrict__ o2,
                                                  int dogelu) {
    int i = blockIdx.x * 256 + threadIdx.x;
    if (i >= MN) return;
    int slab = blockIdx.y;
    int nslab = gridDim.y;
    const float* bias = (slab == 0) ? b0 : ((slab == 1) ? b1 : b2);
    float* out = (slab == 0) ? o0 : ((slab == 1) ? o1 : o2);
    float s = 0.f;
    for (int z = 0; z < nz; z++) s += part[((size_t)z * nslab + slab) * MN + i];
    if (bias) s += bias[i % N];
    if (dogelu) s = 0.5f * s * (1.f + erff(s * 0.70710678118654752440f));
    if (res) s += res[i];
    out[i] = s;
}

// ---------------- attention split kernel (flash-style partials) ----------------
#define SCP 380

__global__ __launch_bounds__(256) void attn_split(const float* __restrict__ q,
                                                  const float* __restrict__ kc,
                                                  const float* __restrict__ vc,
                                                  const float* __restrict__ kn,
                                                  const float* __restrict__ vn,
                                                  const float* __restrict__ mask,
                                                  float* __restrict__ apacc,
                                                  float* __restrict__ aml,
                                                  int Tk, int Tc, int chunk) {
    __shared__ float sc[8 * SCP];
    __shared__ float kt[32 * 68];
    __shared__ float qs[8 * 68];
    __shared__ float ml[16];

    int h = blockIdx.x, b = blockIdx.y, z = blockIdx.z;
    int k0 = z * chunk;
    int nv = min(Tk, k0 + chunk) - k0;
    int tid = threadIdx.x, lane = tid & 31, w = tid >> 5;

    if (tid < 128) {
        int qi = tid >> 4, d4 = (tid & 15) * 4;
        float4 v = *(const float4*)(q + (size_t)(b * TQ + qi) * DD + h * DH + d4);
        v.x *= 0.125f; v.y *= 0.125f; v.z *= 0.125f; v.w *= 0.125f;
        *(float4*)&qs[qi * 68 + d4] = v;
    }
    __syncthreads();

    int qrow = lane >> 2, kslot = lane & 3;
    int krow = w * 4 + kslot;

    for (int kb = 0; kb < nv; kb += 32) {
        int nk = min(32, nv - kb);
        for (int i = tid; i < 512; i += 256) {
            int key = i >> 4, d4 = (i & 15) * 4;
            if (key < nk) {
                int kg = k0 + kb + key;
                const float* src = (kg < Tc)
                    ? kc + ((size_t)b * Tc + kg) * DD + h * DH
                    : kn + (size_t)(b * TQ + (kg - Tc)) * DD + h * DH;
                *(float4*)&kt[key * 68 + d4] = *(const float4*)(src + d4);
            }
        }
        __syncthreads();
        if (krow < nk) {
            const float* qp = &qs[qrow * 68];
            const float* kp = &kt[krow * 68];
            float acc = 0.f;
#pragma unroll
            for (int d = 0; d < 64; d += 4) {
                float4 qv = *(const float4*)(qp + d);
                float4 kv = *(const float4*)(kp + d);
                acc += qv.x * kv.x + qv.y * kv.y + qv.z * kv.z + qv.w * kv.w;
            }
            if (mask) acc += mask[(size_t)qrow * Tk + k0 + kb + krow];
            sc[qrow * SCP + kb + krow] = acc;
        }
        __syncthreads();
    }

    {
        float m = -1e30f;
        for (int k = lane; k < nv; k += 32) m = fmaxf(m, sc[w * SCP + k]);
        for (int o = 16; o; o >>= 1) m = fmaxf(m, __shfl_xor_sync(~0u, m, o));
        float l = 0.f;
        for (int k = lane; k < nv; k += 32) {
            float e = __expf(sc[w * SCP + k] - m);
            sc[w * SCP + k] = e;
            l += e;
        }
        for (int o = 16; o; o >>= 1) l += __shfl_xor_sync(~0u, l, o);
        if (lane == 0) { ml[w * 2] = m; ml[w * 2 + 1] = l; }
    }

    float a0 = 0.f, a1 = 0.f;
    for (int kb = 0; kb < nv; kb += 32) {
        int nk = min(32, nv - kb);
        __syncthreads();
        for (int i = tid; i < 512; i += 256) {
            int key = i >> 4, d4 = (i & 15) * 4;
            if (key < nk) {
                int kg = k0 + kb + key;
                const float* src = (kg < Tc)
                    ? vc + ((size_t)b * Tc + kg) * DD + h * DH
                    : vn + (size_t)(b * TQ + (kg - Tc)) * DD + h * DH;
                *(float4*)&kt[key * 68 + d4] = *(const float4*)(src + d4);
            }
        }
        __syncthreads();
#pragma unroll 4
        for (int k = 0; k < nk; k++) {
            float p = sc[w * SCP + kb + k];
            float2 v2 = *(const float2*)&kt[k * 68 + 2 * lane];
            a0 += p * v2.x;
            a1 += p * v2.y;
        }
    }

    size_t idx = ((size_t)z * BB + b) * HH + h;
    float* ap = apacc + idx * TQ * DH;
    *(float2*)&ap[w * 64 + 2 * lane] = make_float2(a0, a1);
    if (tid < 16) aml[idx * 16 + tid] = ml[tid];
}

// ---------------- attention combine ----------------
__global__ __launch_bounds__(256) void attn_combine(const float* __restrict__ apacc,
                                                    const float* __restrict__ aml,
                                                    float* __restrict__ out, int S) {
    int h = blockIdx.x, b = blockIdx.y;
    int tid = threadIdx.x;
    int qi = tid >> 5, dp = tid & 31;
    float mstar = -1e30f;
    for (int z = 0; z < S; z++) {
        size_t idx = ((size_t)z * BB + b) * HH + h;
        mstar = fmaxf(mstar, aml[idx * 16 + qi * 2]);
    }
    float den = 0.f, n0 = 0.f, n1 = 0.f;
    for (int z = 0; z < S; z++) {
        size_t idx = ((size_t)z * BB + b) * HH + h;
        float mz = aml[idx * 16 + qi * 2];
        float lz = aml[idx * 16 + qi * 2 + 1];
        float s = __expf(mz - mstar);
        den += lz * s;
        float2 a = *(const float2*)&apacc[idx * TQ * DH + qi * 64 + dp * 2];
        n0 += a.x * s;
        n1 += a.y * s;
    }
    float inv = 1.f / den;
    float* o = out + (size_t)(b * TQ + qi) * DD + h * DH + dp * 2;
    o[0] = n0 * inv;
    o[1] = n1 * inv;
}

// ---------------- host orchestration ----------------
extern "C" void kernel_launch(void* const* d_in, const int* in_sizes, int n_in,
                              void* d_out, int out_size) {
    const float* x            = (const float*)d_in[0];
    const float* self_k_cache = (const float*)d_in[1];
    const float* self_v_cache = (const float*)d_in[2];
    const float* cross_k      = (const float*)d_in[3];
    const float* cross_v      = (const float*)d_in[4];
    const float* mask         = (const float*)d_in[5];
    const float* attn_wq = (const float*)d_in[6];
    const float* attn_bq = (const float*)d_in[7];
    const float* attn_wk = (const float*)d_in[8];
    const float* attn_wv = (const float*)d_in[9];
    const float* attn_bv = (const float*)d_in[10];
    const float* attn_wo = (const float*)d_in[11];
    const float* attn_bo = (const float*)d_in[12];
    const float* cross_wq = (const float*)d_in[13];
    const float* cross_bq = (const float*)d_in[14];
    const float* cross_wo = (const float*)d_in[15];
    const float* cross_bo = (const float*)d_in[16];
    const float* attn_ln_w = (const float*)d_in[17];
    const float* attn_ln_b = (const float*)d_in[18];
    const float* cross_ln_w = (const float*)d_in[19];
    const float* cross_ln_b = (const float*)d_in[20];
    const float* mlp_ln_w = (const float*)d_in[21];
    const float* mlp_ln_b = (const float*)d_in[22];
    const float* mlp_w1 = (const float*)d_in[23];
    const float* mlp_b1 = (const float*)d_in[24];
    const float* mlp_w2 = (const float*)d_in[25];
    const float* mlp_b2 = (const float*)d_in[26];

    float* out_x  = (float*)d_out;
    float* out_k1 = out_x + MM * DD;
    float* out_v1 = out_k1 + MM * DD;

    float *g_xl, *g_q, *g_attn, *g_x1, *g_h, *g_part, *g_apacc, *g_aml;
    cudaGetSymbolAddress((void**)&g_xl, g_xl_);
    cudaGetSymbolAddress((void**)&g_q, g_q_);
    cudaGetSymbolAddress((void**)&g_attn, g_attn_);
    cudaGetSymbolAddress((void**)&g_x1, g_x1_);
    cudaGetSymbolAddress((void**)&g_h, g_h_);
    cudaGetSymbolAddress((void**)&g_part, g_part_);
    cudaGetSymbolAddress((void**)&g_apacc, g_apacc_);
    cudaGetSymbolAddress((void**)&g_aml, g_aml_);

    const int MN_D = MM * DD;        // 81920
    const int MN_F = MM * DFF;       // 327680
    dim3 blk(256);

    // GEMM configs (N-tile 64, K-tile 32): deep split-K for multi-wave occupancy.
    dim3 gQKV(DD / 64, 3, 20);   // fused QKV: kc=64 (2 stages), 1200 CTAs
    dim3 gD(DD / 64, 1, 20);     // D GEMM: kc=64 (2 stages), 400 CTAs
    dim3 gF1(DFF / 64, 1, 8);    // MLP1: kc=160 (5 stages), 640 CTAs
    dim3 gF2(DD / 64, 1, 20);    // MLP2: kc=256 (8 stages), 400 CTAs
    int redD = (MN_D + 255) / 256;
    int redF = (MN_F + 255) / 256;

    int S_SELF = 4, CH_SELF = (TK_SELF + S_SELF - 1) / S_SELF;   // 114
    int S_CROSS = 10, CH_CROSS = TC / S_CROSS;                   // 150

    // --- self-attention block ---
    ln_kernel<<<MM, blk>>>(x, attn_ln_w, attn_ln_b, g_xl);

    gemm_mma<<<gQKV, blk>>>(g_xl, attn_wq, attn_wk, attn_wv, g_part, DD, DD, 64);
    reduce_epi<<<dim3(redD, 3), blk>>>(g_part, 20, MN_D, DD,
                                       attn_bq, nullptr, attn_bv, nullptr,
                                       g_q, out_k1, out_v1, 0);

    attn_split<<<dim3(HH, BB, S_SELF), blk>>>(g_q, self_k_cache, self_v_cache,
                                              out_k1, out_v1, mask,
                                              g_apacc, g_aml, TK_SELF, TP, CH_SELF);
    attn_combine<<<dim3(HH, BB), blk>>>(g_apacc, g_aml, g_attn, S_SELF);

    gemm_mma<<<gD, blk>>>(g_attn, attn_wo, attn_wo, attn_wo, g_part, DD, DD, 64);
    reduce_epi<<<dim3(redD, 1), blk>>>(g_part, 20, MN_D, DD,
                                       attn_bo, nullptr, nullptr, x,
                                       g_x1, nullptr, nullptr, 0);

    // --- cross-attention block ---
    ln_kernel<<<MM, blk>>>(g_x1, cross_ln_w, cross_ln_b, g_xl);

    gemm_mma<<<gD, blk>>>(g_xl, cross_wq, cross_wq, cross_wq, g_part, DD, DD, 64);
    reduce_epi<<<dim3(redD, 1), blk>>>(g_part, 20, MN_D, DD,
                                       cross_bq, nullptr, nullptr, nullptr,
                                       g_q, nullptr, nullptr, 0);

    attn_split<<<dim3(HH, BB, S_CROSS), blk>>>(g_q, cross_k, cross_v,
                                               nullptr, nullptr, nullptr,
                                               g_apacc, g_aml, TC, TC, CH_CROSS);
    attn_combine<<<dim3(HH, BB), blk>>>(g_apacc, g_aml, g_attn, S_CROSS);

    gemm_mma<<<gD, blk>>>(g_attn, cross_wo, cross_wo, cross_wo, g_part, DD, DD, 64);
    reduce_epi<<<dim3(redD, 1), blk>>>(g_part, 20, MN_D, DD,
                                       cross_bo, nullptr, nullptr, g_x1,
                                       out_x, nullptr, nullptr, 0);

    // --- MLP block ---
    ln_kernel<<<MM, blk>>>(out_x, mlp_ln_w, mlp_ln_b, g_xl);

    gemm_mma<<<gF1, blk>>>(g_xl, mlp_w1, mlp_w1, mlp_w1, g_part, DD, DFF, 160);
    reduce_epi<<<dim3(redF, 1), blk>>>(g_part, 8, MN_F, DFF,
                                       mlp_b1, nullptr, nullptr, nullptr,
                                       g_h, nullptr, nullptr, 1);

    gemm_mma<<<gF2, blk>>>(g_h, mlp_w2, mlp_w2, mlp_w2, g_part, DFF, DD, 256);
    reduce_epi<<<dim3(redD, 1), blk>>>(g_part, 20, MN_D, DD,
                                       mlp_b2, nullptr, nullptr, out_x,
                                       out_x, nullptr, nullptr, 0);
}

// round 10
// speedup vs baseline: 2.1955x; 1.0986x over previous
#include <cuda_runtime.h>
#include <cuda_bf16.h>
#include <cstdint>
#include <math.h>

// ---------------- problem constants ----------------
#define BB 8
#define TQ 8
#define TP 447
#define TC 1500
#define DD 1280
#define HH 20
#define DH 64
#define DFF 5120
#define MM 64              // B*TQ rows
#define TK_SELF (TP + TQ)  // 455

// ---------------- scratch (device globals; no allocation allowed) ----------------
__device__ float g_xl_[MM * DD];
__device__ float g_q_[MM * DD];
__device__ float g_attn_[MM * DD];
__device__ float g_x1_[MM * DD];
__device__ float g_h_[MM * DFF];
__device__ float g_part_[4915200];                  // split-K partials
__device__ float g_apacc_[16 * BB * HH * TQ * DH];  // attn split partial acc
__device__ float g_aml_[16 * BB * HH * 16];         // attn split (m,l) per q

// ---------------- helpers ----------------
__device__ __forceinline__ uint32_t smem_to_u32(const void* p) {
    uint32_t a;
    asm("{ .reg .u64 t; cvta.to.shared.u64 t, %1; cvt.u32.u64 %0, t; }" : "=r"(a) : "l"(p));
    return a;
}
__device__ __forceinline__ uint32_t f2tf(float f) {
    uint32_t r;
    asm("cvt.rna.tf32.f32 %0, %1;" : "=r"(r) : "f"(f));
    return r;
}
#define LDMX4(r0, r1, r2, r3, addr) \
    asm volatile("ldmatrix.sync.aligned.m8n8.x4.shared.b16 {%0,%1,%2,%3}, [%4];" \
                 : "=r"(r0), "=r"(r1), "=r"(r2), "=r"(r3) : "r"(addr))
__device__ __forceinline__ void mma_tf32(float c[4], uint32_t a0, uint32_t a1,
                                         uint32_t a2, uint32_t a3,
                                         uint32_t b0, uint32_t b1) {
    asm volatile(
        "mma.sync.aligned.m16n8k8.row.col.f32.tf32.tf32.f32 "
        "{%0,%1,%2,%3}, {%4,%5,%6,%7}, {%8,%9}, {%0,%1,%2,%3};"
        : "+f"(c[0]), "+f"(c[1]), "+f"(c[2]), "+f"(c[3])
        : "r"(a0), "r"(a1), "r"(a2), "r"(a3), "r"(b0), "r"(b1));
}
#define CP_ASYNC16(saddr, gptr) \
    asm volatile("cp.async.cg.shared.global [%0], [%1], 16;" :: "r"(saddr), "l"(gptr))
#define CP_COMMIT() asm volatile("cp.async.commit_group;" ::: "memory")
#define CP_WAIT1() asm volatile("cp.async.wait_group 1;" ::: "memory")
#define CP_WAIT0() asm volatile("cp.async.wait_group 0;" ::: "memory")

// ---------------- LayerNorm: one block per row ----------------
__global__ __launch_bounds__(256) void ln_kernel(const float* __restrict__ x,
                                                 const float* __restrict__ w,
                                                 const float* __restrict__ b,
                                                 float* __restrict__ out) {
    int row = blockIdx.x;
    const float* xr = x + (size_t)row * DD;
    __shared__ float red0[32], red1[32];
    float s = 0.f, s2 = 0.f;
    for (int i = threadIdx.x; i < DD; i += 256) {
        float v = xr[i];
        s += v;
        s2 += v * v;
    }
    for (int o = 16; o; o >>= 1) {
        s += __shfl_xor_sync(~0u, s, o);
        s2 += __shfl_xor_sync(~0u, s2, o);
    }
    int lane = threadIdx.x & 31, wid = threadIdx.x >> 5;
    if (lane == 0) { red0[wid] = s; red1[wid] = s2; }
    __syncthreads();
    if (wid == 0) {
        s = (lane < 8) ? red0[lane] : 0.f;
        s2 = (lane < 8) ? red1[lane] : 0.f;
        for (int o = 4; o; o >>= 1) {
            s += __shfl_xor_sync(~0u, s, o);
            s2 += __shfl_xor_sync(~0u, s2, o);
        }
        if (lane == 0) { red0[0] = s; red1[0] = s2; }
    }
    __syncthreads();
    float m = red0[0] * (1.f / DD);
    float var = red1[0] * (1.f / DD) - m * m;
    float inv = rsqrtf(var + 1e-5f);
    for (int i = threadIdx.x; i < DD; i += 256) {
        out[(size_t)row * DD + i] = (xr[i] - m) * inv * w[i] + b[i];
    }
}

// ---------------- mma.sync tf32 split-K GEMM ----------------
// blockIdx.y selects weight slab (fused QKV); partials layout [z][slab][64][N].
#define SA 36   // smem row stride in floats

__global__ __launch_bounds__(256) void gemm_mma(const float* __restrict__ A,
                                                const float* __restrict__ W0,
                                                const float* __restrict__ W1,
                                                const float* __restrict__ W2,
                                                float* __restrict__ part,
                                                int K, int N, int kc) {
    __shared__ __align__(16) uint32_t As[2][64 * SA];
    __shared__ __align__(16) uint32_t Bs[2][64 * SA];
    int tid = threadIdx.x, lane = tid & 31, w = tid >> 5;
    int wm = w & 3, wn = w >> 2;
    int n0 = blockIdx.x * 64;
    int slab = blockIdx.y;
    const float* W = (slab == 0) ? W0 : ((slab == 1) ? W1 : W2);
    int z = blockIdx.z, k0 = z * kc;
    int nst = kc >> 5;

    int a_row = wm * 16 + ((lane >> 3) & 1) * 8 + (lane & 7);
    uint32_t a_koff = ((lane >> 4) & 1) * 16;
    int b_row_off = ((lane >> 4) & 1) * 8 + (lane & 7);
    uint32_t b_koff = ((lane >> 3) & 1) * 16;
    uint32_t aAddr0 = smem_to_u32(&As[0][0]) + (uint32_t)(a_row * SA) * 4 + a_koff;
    uint32_t bAddr0 = smem_to_u32(&Bs[0][0]) + b_koff;

    int s_row = tid >> 2, s_c4 = tid & 3;
    int s_n = tid & 63, s_k = tid >> 6;

    float c[4][4];
#pragma unroll
    for (int j = 0; j < 4; j++)
#pragma unroll
        for (int i = 0; i < 4; i++) c[j][i] = 0.f;

    {
        const float* ar = A + (size_t)s_row * K + k0;
        float4 v0 = *(const float4*)(ar + s_c4 * 4);
        float4 v1 = *(const float4*)(ar + (s_c4 + 4) * 4);
        uint4 u0 = make_uint4(f2tf(v0.x), f2tf(v0.y), f2tf(v0.z), f2tf(v0.w));
        uint4 u1 = make_uint4(f2tf(v1.x), f2tf(v1.y), f2tf(v1.z), f2tf(v1.w));
        *(uint4*)&As[0][s_row * SA + s_c4 * 4] = u0;
        *(uint4*)&As[0][s_row * SA + (s_c4 + 4) * 4] = u1;
        const float* wp = W + (size_t)k0 * N + n0 + s_n;
#pragma unroll
        for (int j = 0; j < 8; j++) {
            int k2 = s_k + j * 4;
            Bs[0][s_n * SA + k2] = f2tf(wp[(size_t)k2 * N]);
        }
    }
    __syncthreads();

    for (int st = 0; st < nst; st++) {
        int buf = st & 1;
        float4 pa0, pa1;
        float pb[8];
        if (st + 1 < nst) {
            int kb = k0 + (st + 1) * 32;
            const float* ar = A + (size_t)s_row * K + kb;
            pa0 = *(const float4*)(ar + s_c4 * 4);
            pa1 = *(const float4*)(ar + (s_c4 + 4) * 4);
            const float* wp = W + (size_t)kb * N + n0 + s_n;
#pragma unroll
            for (int j = 0; j < 8; j++) pb[j] = wp[(size_t)(s_k + j * 4) * N];
        }
        uint32_t aB = aAddr0 + (uint32_t)buf * 64 * SA * 4;
#pragma unroll
        for (int s = 0; s < 4; s++) {
            uint32_t a0, a1, a2, a3;
            LDMX4(a0, a1, a2, a3, aB + s * 32);
#pragma unroll
            for (int jp = 0; jp < 2; jp++) {
                uint32_t b0, b1, b2, b3;
                uint32_t baddr = bAddr0 + (uint32_t)buf * 64 * SA * 4 +
                                 (uint32_t)((wn * 32 + jp * 16 + b_row_off) * SA) * 4 + s * 32;
                LDMX4(b0, b1, b2, b3, baddr);
                mma_tf32(c[jp * 2], a0, a1, a2, a3, b0, b1);
                mma_tf32(c[jp * 2 + 1], a0, a1, a2, a3, b2, b3);
            }
        }
        if (st + 1 < nst) {
            int nb = buf ^ 1;
            uint4 u0 = make_uint4(f2tf(pa0.x), f2tf(pa0.y), f2tf(pa0.z), f2tf(pa0.w));
            uint4 u1 = make_uint4(f2tf(pa1.x), f2tf(pa1.y), f2tf(pa1.z), f2tf(pa1.w));
            *(uint4*)&As[nb][s_row * SA + s_c4 * 4] = u0;
            *(uint4*)&As[nb][s_row * SA + (s_c4 + 4) * 4] = u1;
#pragma unroll
            for (int j = 0; j < 8; j++)
                Bs[nb][s_n * SA + s_k + j * 4] = f2tf(pb[j]);
            __syncthreads();
        }
    }

    int g = lane >> 2, t = lane & 3;
    float* po = part + ((size_t)z * gridDim.y + slab) * MM * N;
#pragma unroll
    for (int j = 0; j < 4; j++) {
        int col = n0 + wn * 32 + j * 8 + 2 * t;
        int r0 = wm * 16 + g;
        *(float2*)&po[(size_t)r0 * N + col] = make_float2(c[j][0], c[j][1]);
        *(float2*)&po[(size_t)(r0 + 8) * N + col] = make_float2(c[j][2], c[j][3]);
    }
}

// ---------------- reduce partials + epilogue (multi-slab) ----------------
__global__ __launch_bounds__(256) void reduce_epi(const float* __restrict__ part, int nz,
                                                  int MN, int N,
                                                  const float* __restrict__ b0,
                                                  const float* __restrict__ b1,
                                                  const float* __restrict__ b2,
                                                  const float* __restrict__ res,
                                                  float* __restrict__ o0,
                                                  float* __restrict__ o1,
                                                  float* __restrict__ o2,
                                                  int dogelu) {
    int i = blockIdx.x * 256 + threadIdx.x;
    if (i >= MN) return;
    int slab = blockIdx.y;
    int nslab = gridDim.y;
    const float* bias = (slab == 0) ? b0 : ((slab == 1) ? b1 : b2);
    float* out = (slab == 0) ? o0 : ((slab == 1) ? o1 : o2);
    float s = 0.f;
    for (int z = 0; z < nz; z++) s += part[((size_t)z * nslab + slab) * MN + i];
    if (bias) s += bias[i % N];
    if (dogelu) s = 0.5f * s * (1.f + erff(s * 0.70710678118654752440f));
    if (res) s += res[i];
    out[i] = s;
}

// ---------------- attention split kernel (cp.async double-buffered tiles) ----
#define SCP 152
#define KTILE_F (32 * 68)     // floats per tile buffer

__global__ __launch_bounds__(256) void attn_split(const float* __restrict__ kq,
                                                  const float* __restrict__ kc,
                                                  const float* __restrict__ vc,
                                                  const float* __restrict__ kn,
                                                  const float* __restrict__ vn,
                                                  const float* __restrict__ mask,
                                                  float* __restrict__ apacc,
                                                  float* __restrict__ aml,
                                                  int Tk, int Tc, int chunk) {
    __shared__ float sc[8 * SCP];
    __shared__ __align__(16) float kt[2][KTILE_F];
    __shared__ float qs[8 * 68];
    __shared__ float ml[16];

    int h = blockIdx.x, b = blockIdx.y, z = blockIdx.z;
    int k0 = z * chunk;
    int nv = min(Tk, k0 + chunk) - k0;
    int tid = threadIdx.x, lane = tid & 31, w = tid >> 5;
    uint32_t ktb = smem_to_u32(&kt[0][0]);

    if (tid < 128) {
        int qi = tid >> 4, d4 = (tid & 15) * 4;
        float4 v = *(const float4*)(kq + (size_t)(b * TQ + qi) * DD + h * DH + d4);
        v.x *= 0.125f; v.y *= 0.125f; v.z *= 0.125f; v.w *= 0.125f;
        *(float4*)&qs[qi * 68 + d4] = v;
    }
    __syncthreads();

    int qrow = lane >> 2, kslot = lane & 3;
    int krow = w * 4 + kslot;
    int s_key = tid >> 4, s_d4 = (tid & 15) * 4;      // staging: 2 iters/thread
    int nt = (nv + 31) >> 5;

    // ==== pass 1: scores ====
    {   // prologue: tile 0
        int nk0 = min(32, nv);
#pragma unroll
        for (int rep = 0; rep < 2; rep++) {
            int key = s_key + rep * 16;
            if (key < nk0) {
                int kg = k0 + key;
                const float* src = (kg < Tc)
                    ? kc + ((size_t)b * Tc + kg) * DD + h * DH
                    : kn + (size_t)(b * TQ + (kg - Tc)) * DD + h * DH;
                CP_ASYNC16(ktb + (uint32_t)(key * 68 + s_d4) * 4, src + s_d4);
            }
        }
        CP_COMMIT();
    }
    for (int t = 0; t < nt; t++) {
        int kb = t * 32;
        int nk = min(32, nv - kb);
        if (t + 1 < nt) {
            int kb2 = (t + 1) * 32;
            int nk2 = min(32, nv - kb2);
            uint32_t dst = ktb + (uint32_t)(((t + 1) & 1) * KTILE_F) * 4;
#pragma unroll
            for (int rep = 0; rep < 2; rep++) {
                int key = s_key + rep * 16;
                if (key < nk2) {
                    int kg = k0 + kb2 + key;
                    const float* src = (kg < Tc)
                        ? kc + ((size_t)b * Tc + kg) * DD + h * DH
                        : kn + (size_t)(b * TQ + (kg - Tc)) * DD + h * DH;
                    CP_ASYNC16(dst + (uint32_t)(key * 68 + s_d4) * 4, src + s_d4);
                }
            }
            CP_COMMIT();
            CP_WAIT1();
        } else {
            CP_WAIT0();
        }
        __syncthreads();
        if (krow < nk) {
            const float* qp = &qs[qrow * 68];
            const float* kp = &kt[t & 1][krow * 68];
            float acc = 0.f;
#pragma unroll
            for (int d = 0; d < 64; d += 4) {
                float4 qv = *(const float4*)(qp + d);
                float4 kv = *(const float4*)(kp + d);
                acc += qv.x * kv.x + qv.y * kv.y + qv.z * kv.z + qv.w * kv.w;
            }
            if (mask) acc += mask[(size_t)qrow * Tk + k0 + kb + krow];
            sc[qrow * SCP + kb + krow] = acc;
        }
        __syncthreads();
    }

    // ==== partial softmax: warp w owns q row w ====
    {
        float m = -1e30f;
        for (int k = lane; k < nv; k += 32) m = fmaxf(m, sc[w * SCP + k]);
        for (int o = 16; o; o >>= 1) m = fmaxf(m, __shfl_xor_sync(~0u, m, o));
        float l = 0.f;
        for (int k = lane; k < nv; k += 32) {
            float e = __expf(sc[w * SCP + k] - m);
            sc[w * SCP + k] = e;
            l += e;
        }
        for (int o = 16; o; o >>= 1) l += __shfl_xor_sync(~0u, l, o);
        if (lane == 0) { ml[w * 2] = m; ml[w * 2 + 1] = l; }
    }
    __syncthreads();

    // ==== pass 2: AV ====
    float a0 = 0.f, a1 = 0.f;
    {   // prologue: V tile 0
        int nk0 = min(32, nv);
#pragma unroll
        for (int rep = 0; rep < 2; rep++) {
            int key = s_key + rep * 16;
            if (key < nk0) {
                int kg = k0 + key;
                const float* src = (kg < Tc)
                    ? vc + ((size_t)b * Tc + kg) * DD + h * DH
                    : vn + (size_t)(b * TQ + (kg - Tc)) * DD + h * DH;
                CP_ASYNC16(ktb + (uint32_t)(key * 68 + s_d4) * 4, src + s_d4);
            }
        }
        CP_COMMIT();
    }
    for (int t = 0; t < nt; t++) {
        int kb = t * 32;
        int nk = min(32, nv - kb);
        if (t + 1 < nt) {
            int kb2 = (t + 1) * 32;
            int nk2 = min(32, nv - kb2);
            uint32_t dst = ktb + (uint32_t)(((t + 1) & 1) * KTILE_F) * 4;
#pragma unroll
            for (int rep = 0; rep < 2; rep++) {
                int key = s_key + rep * 16;
                if (key < nk2) {
                    int kg = k0 + kb2 + key;
                    const float* src = (kg < Tc)
                        ? vc + ((size_t)b * Tc + kg) * DD + h * DH
                        : vn + (size_t)(b * TQ + (kg - Tc)) * DD + h * DH;
                    CP_ASYNC16(dst + (uint32_t)(key * 68 + s_d4) * 4, src + s_d4);
                }
            }
            CP_COMMIT();
            CP_WAIT1();
        } else {
            CP_WAIT0();
        }
        __syncthreads();
        const float* vt = &kt[t & 1][0];
#pragma unroll 4
        for (int k = 0; k < nk; k++) {
            float p = sc[w * SCP + kb + k];
            float2 v2 = *(const float2*)&vt[k * 68 + 2 * lane];
            a0 += p * v2.x;
            a1 += p * v2.y;
        }
        __syncthreads();
    }

    size_t idx = ((size_t)z * BB + b) * HH + h;
    float* ap = apacc + idx * TQ * DH;
    *(float2*)&ap[w * 64 + 2 * lane] = make_float2(a0, a1);
    if (tid < 16) aml[idx * 16 + tid] = ml[tid];
}

// ---------------- attention combine ----------------
__global__ __launch_bounds__(256) void attn_combine(const float* __restrict__ apacc,
                                                    const float* __restrict__ aml,
                                                    float* __restrict__ out, int S) {
    int h = blockIdx.x, b = blockIdx.y;
    int tid = threadIdx.x;
    int qi = tid >> 5, dp = tid & 31;
    float mstar = -1e30f;
    for (int z = 0; z < S; z++) {
        size_t idx = ((size_t)z * BB + b) * HH + h;
        mstar = fmaxf(mstar, aml[idx * 16 + qi * 2]);
    }
    float den = 0.f, n0 = 0.f, n1 = 0.f;
    for (int z = 0; z < S; z++) {
        size_t idx = ((size_t)z * BB + b) * HH + h;
        float mz = aml[idx * 16 + qi * 2];
        float lz = aml[idx * 16 + qi * 2 + 1];
        float s = __expf(mz - mstar);
        den += lz * s;
        float2 a = *(const float2*)&apacc[idx * TQ * DH + qi * 64 + dp * 2];
        n0 += a.x * s;
        n1 += a.y * s;
    }
    float inv = 1.f / den;
    float* o = out + (size_t)(b * TQ + qi) * DD + h * DH + dp * 2;
    o[0] = n0 * inv;
    o[1] = n1 * inv;
}

// ---------------- host orchestration ----------------
extern "C" void kernel_launch(void* const* d_in, const int* in_sizes, int n_in,
                              void* d_out, int out_size) {
    const float* x            = (const float*)d_in[0];
    const float* self_k_cache = (const float*)d_in[1];
    const float* self_v_cache = (const float*)d_in[2];
    const float* cross_k      = (const float*)d_in[3];
    const float* cross_v      = (const float*)d_in[4];
    const float* mask         = (const float*)d_in[5];
    const float* attn_wq = (const float*)d_in[6];
    const float* attn_bq = (const float*)d_in[7];
    const float* attn_wk = (const float*)d_in[8];
    const float* attn_wv = (const float*)d_in[9];
    const float* attn_bv = (const float*)d_in[10];
    const float* attn_wo = (const float*)d_in[11];
    const float* attn_bo = (const float*)d_in[12];
    const float* cross_wq = (const float*)d_in[13];
    const float* cross_bq = (const float*)d_in[14];
    const float* cross_wo = (const float*)d_in[15];
    const float* cross_bo = (const float*)d_in[16];
    const float* attn_ln_w = (const float*)d_in[17];
    const float* attn_ln_b = (const float*)d_in[18];
    const float* cross_ln_w = (const float*)d_in[19];
    const float* cross_ln_b = (const float*)d_in[20];
    const float* mlp_ln_w = (const float*)d_in[21];
    const float* mlp_ln_b = (const float*)d_in[22];
    const float* mlp_w1 = (const float*)d_in[23];
    const float* mlp_b1 = (const float*)d_in[24];
    const float* mlp_w2 = (const float*)d_in[25];
    const float* mlp_b2 = (const float*)d_in[26];

    float* out_x  = (float*)d_out;
    float* out_k1 = out_x + MM * DD;
    float* out_v1 = out_k1 + MM * DD;

    float *g_xl, *g_q, *g_attn, *g_x1, *g_h, *g_part, *g_apacc, *g_aml;
    cudaGetSymbolAddress((void**)&g_xl, g_xl_);
    cudaGetSymbolAddress((void**)&g_q, g_q_);
    cudaGetSymbolAddress((void**)&g_attn, g_attn_);
    cudaGetSymbolAddress((void**)&g_x1, g_x1_);
    cudaGetSymbolAddress((void**)&g_h, g_h_);
    cudaGetSymbolAddress((void**)&g_part, g_part_);
    cudaGetSymbolAddress((void**)&g_apacc, g_apacc_);
    cudaGetSymbolAddress((void**)&g_aml, g_aml_);

    const int MN_D = MM * DD;        // 81920
    const int MN_F = MM * DFF;       // 327680
    dim3 blk(256);

    dim3 gQKV(DD / 64, 3, 10);   // fused QKV: kc=128 (4 stages), 600 CTAs
    dim3 gD(DD / 64, 1, 20);     // D GEMM: kc=64 (2 stages), 400 CTAs
    dim3 gF1(DFF / 64, 1, 8);    // MLP1: kc=160 (5 stages), 640 CTAs
    dim3 gF2(DD / 64, 1, 20);    // MLP2: kc=256 (8 stages), 400 CTAs
    int redD = (MN_D + 255) / 256;
    int redF = (MN_F + 255) / 256;

    int S_SELF = 6, CH_SELF = (TK_SELF + S_SELF - 1) / S_SELF;   // 76
    int S_CROSS = 10, CH_CROSS = TC / S_CROSS;                   // 150

    // --- self-attention block ---
    ln_kernel<<<MM, blk>>>(x, attn_ln_w, attn_ln_b, g_xl);

    gemm_mma<<<gQKV, blk>>>(g_xl, attn_wq, attn_wk, attn_wv, g_part, DD, DD, 128);
    reduce_epi<<<dim3(redD, 3), blk>>>(g_part, 10, MN_D, DD,
                                       attn_bq, nullptr, attn_bv, nullptr,
                                       g_q, out_k1, out_v1, 0);

    attn_split<<<dim3(HH, BB, S_SELF), blk>>>(g_q, self_k_cache, self_v_cache,
                                              out_k1, out_v1, mask,
                                              g_apacc, g_aml, TK_SELF, TP, CH_SELF);
    attn_combine<<<dim3(HH, BB), blk>>>(g_apacc, g_aml, g_attn, S_SELF);

    gemm_mma<<<gD, blk>>>(g_attn, attn_wo, attn_wo, attn_wo, g_part, DD, DD, 64);
    reduce_epi<<<dim3(redD, 1), blk>>>(g_part, 20, MN_D, DD,
                                       attn_bo, nullptr, nullptr, x,
                                       g_x1, nullptr, nullptr, 0);

    // --- cross-attention block ---
    ln_kernel<<<MM, blk>>>(g_x1, cross_ln_w, cross_ln_b, g_xl);

    gemm_mma<<<gD, blk>>>(g_xl, cross_wq, cross_wq, cross_wq, g_part, DD, DD, 64);
    reduce_epi<<<dim3(redD, 1), blk>>>(g_part, 20, MN_D, DD,
                                       cross_bq, nullptr, nullptr, nullptr,
                                       g_q, nullptr, nullptr, 0);

    attn_split<<<dim3(HH, BB, S_CROSS), blk>>>(g_q, cross_k, cross_v,
                                               nullptr, nullptr, nullptr,
                                               g_apacc, g_aml, TC, TC, CH_CROSS);
    attn_combine<<<dim3(HH, BB), blk>>>(g_apacc, g_aml, g_attn, S_CROSS);

    gemm_mma<<<gD, blk>>>(g_attn, cross_wo, cross_wo, cross_wo, g_part, DD, DD, 64);
    reduce_epi<<<dim3(redD, 1), blk>>>(g_part, 20, MN_D, DD,
                                       cross_bo, nullptr, nullptr, g_x1,
                                       out_x, nullptr, nullptr, 0);

    // --- MLP block ---
    ln_kernel<<<MM, blk>>>(out_x, mlp_ln_w, mlp_ln_b, g_xl);

    gemm_mma<<<gF1, blk>>>(g_xl, mlp_w1, mlp_w1, mlp_w1, g_part, DD, DFF, 160);
    reduce_epi<<<dim3(redF, 1), blk>>>(g_part, 8, MN_F, DFF,
                                       mlp_b1, nullptr, nullptr, nullptr,
                                       g_h, nullptr, nullptr, 1);

    gemm_mma<<<gF2, blk>>>(g_h, mlp_w2, mlp_w2, mlp_w2, g_part, DFF, DD, 256);
    reduce_epi<<<dim3(redD, 1), blk>>>(g_part, 20, MN_D, DD,
                                       mlp_b2, nullptr, nullptr, out_x,
                                       out_x, nullptr, nullptr, 0);
}

// round 11
// speedup vs baseline: 2.2844x; 1.0405x over previous
#include <cuda_runtime.h>
#include <cuda_bf16.h>
#include <cstdint>
#include <math.h>

// ---------------- problem constants ----------------
#define BB 8
#define TQ 8
#define TP 447
#define TC 1500
#define DD 1280
#define HH 20
#define DH 64
#define DFF 5120
#define MM 64              // B*TQ rows
#define TK_SELF (TP + TQ)  // 455

// ---------------- scratch (device globals; no allocation allowed) ----------------
__device__ float g_xl_[MM * DD];
__device__ float g_q_[MM * DD];
__device__ float g_attn_[MM * DD];
__device__ float g_x1_[MM * DD];
__device__ float g_h_[MM * DFF];
__device__ float g_part_[4915200];                  // split-K partials
__device__ float g_apacc_[16 * BB * HH * TQ * DH];  // attn split partial acc
__device__ float g_aml_[16 * BB * HH * 16];         // attn split (m,l) per q

// ---------------- helpers ----------------
__device__ __forceinline__ uint32_t smem_to_u32(const void* p) {
    uint32_t a;
    asm("{ .reg .u64 t; cvta.to.shared.u64 t, %1; cvt.u32.u64 %0, t; }" : "=r"(a) : "l"(p));
    return a;
}
__device__ __forceinline__ uint32_t f2tf(float f) {
    uint32_t r;
    asm("cvt.rna.tf32.f32 %0, %1;" : "=r"(r) : "f"(f));
    return r;
}
#define LDMX4(r0, r1, r2, r3, addr) \
    asm volatile("ldmatrix.sync.aligned.m8n8.x4.shared.b16 {%0,%1,%2,%3}, [%4];" \
                 : "=r"(r0), "=r"(r1), "=r"(r2), "=r"(r3) : "r"(addr))
__device__ __forceinline__ void mma_tf32(float c[4], uint32_t a0, uint32_t a1,
                                         uint32_t a2, uint32_t a3,
                                         uint32_t b0, uint32_t b1) {
    asm volatile(
        "mma.sync.aligned.m16n8k8.row.col.f32.tf32.tf32.f32 "
        "{%0,%1,%2,%3}, {%4,%5,%6,%7}, {%8,%9}, {%0,%1,%2,%3};"
        : "+f"(c[0]), "+f"(c[1]), "+f"(c[2]), "+f"(c[3])
        : "r"(a0), "r"(a1), "r"(a2), "r"(a3), "r"(b0), "r"(b1));
}
#define CP_ASYNC16(saddr, gptr) \
    asm volatile("cp.async.cg.shared.global [%0], [%1], 16;" :: "r"(saddr), "l"(gptr))
#define CP_COMMIT() asm volatile("cp.async.commit_group;" ::: "memory")
#define CP_WAIT1() asm volatile("cp.async.wait_group 1;" ::: "memory")
#define CP_WAIT0() asm volatile("cp.async.wait_group 0;" ::: "memory")

// ---------------- LayerNorm: one block per row ----------------
__global__ __launch_bounds__(256) void ln_kernel(const float* __restrict__ x,
                                                 const float* __restrict__ w,
                                                 const float* __restrict__ b,
                                                 float* __restrict__ out) {
    int row = blockIdx.x;
    const float* xr = x + (size_t)row * DD;
    __shared__ float red0[32], red1[32];
    float s = 0.f, s2 = 0.f;
    for (int i = threadIdx.x; i < DD; i += 256) {
        float v = xr[i];
        s += v;
        s2 += v * v;
    }
    for (int o = 16; o; o >>= 1) {
        s += __shfl_xor_sync(~0u, s, o);
        s2 += __shfl_xor_sync(~0u, s2, o);
    }
    int lane = threadIdx.x & 31, wid = threadIdx.x >> 5;
    if (lane == 0) { red0[wid] = s; red1[wid] = s2; }
    __syncthreads();
    if (wid == 0) {
        s = (lane < 8) ? red0[lane] : 0.f;
        s2 = (lane < 8) ? red1[lane] : 0.f;
        for (int o = 4; o; o >>= 1) {
            s += __shfl_xor_sync(~0u, s, o);
            s2 += __shfl_xor_sync(~0u, s2, o);
        }
        if (lane == 0) { red0[0] = s; red1[0] = s2; }
    }
    __syncthreads();
    float m = red0[0] * (1.f / DD);
    float var = red1[0] * (1.f / DD) - m * m;
    float inv = rsqrtf(var + 1e-5f);
    for (int i = threadIdx.x; i < DD; i += 256) {
        out[(size_t)row * DD + i] = (xr[i] - m) * inv * w[i] + b[i];
    }
}

// ---------------- mma.sync tf32 split-K GEMM ----------------
#define SA 36   // smem row stride in floats

__global__ __launch_bounds__(256) void gemm_mma(const float* __restrict__ A,
                                                const float* __restrict__ W0,
                                                const float* __restrict__ W1,
                                                const float* __restrict__ W2,
                                                float* __restrict__ part,
                                                int K, int N, int kc) {
    __shared__ __align__(16) uint32_t As[2][64 * SA];
    __shared__ __align__(16) uint32_t Bs[2][64 * SA];
    int tid = threadIdx.x, lane = tid & 31, w = tid >> 5;
    int wm = w & 3, wn = w >> 2;
    int n0 = blockIdx.x * 64;
    int slab = blockIdx.y;
    const float* W = (slab == 0) ? W0 : ((slab == 1) ? W1 : W2);
    int z = blockIdx.z, k0 = z * kc;
    int nst = kc >> 5;

    int a_row = wm * 16 + ((lane >> 3) & 1) * 8 + (lane & 7);
    uint32_t a_koff = ((lane >> 4) & 1) * 16;
    int b_row_off = ((lane >> 4) & 1) * 8 + (lane & 7);
    uint32_t b_koff = ((lane >> 3) & 1) * 16;
    uint32_t aAddr0 = smem_to_u32(&As[0][0]) + (uint32_t)(a_row * SA) * 4 + a_koff;
    uint32_t bAddr0 = smem_to_u32(&Bs[0][0]) + b_koff;

    int s_row = tid >> 2, s_c4 = tid & 3;
    int s_n = tid & 63, s_k = tid >> 6;

    float c[4][4];
#pragma unroll
    for (int j = 0; j < 4; j++)
#pragma unroll
        for (int i = 0; i < 4; i++) c[j][i] = 0.f;

    {
        const float* ar = A + (size_t)s_row * K + k0;
        float4 v0 = *(const float4*)(ar + s_c4 * 4);
        float4 v1 = *(const float4*)(ar + (s_c4 + 4) * 4);
        uint4 u0 = make_uint4(f2tf(v0.x), f2tf(v0.y), f2tf(v0.z), f2tf(v0.w));
        uint4 u1 = make_uint4(f2tf(v1.x), f2tf(v1.y), f2tf(v1.z), f2tf(v1.w));
        *(uint4*)&As[0][s_row * SA + s_c4 * 4] = u0;
        *(uint4*)&As[0][s_row * SA + (s_c4 + 4) * 4] = u1;
        const float* wp = W + (size_t)k0 * N + n0 + s_n;
#pragma unroll
        for (int j = 0; j < 8; j++) {
            int k2 = s_k + j * 4;
            Bs[0][s_n * SA + k2] = f2tf(wp[(size_t)k2 * N]);
        }
    }
    __syncthreads();

    for (int st = 0; st < nst; st++) {
        int buf = st & 1;
        float4 pa0, pa1;
        float pb[8];
        if (st + 1 < nst) {
            int kb = k0 + (st + 1) * 32;
            const float* ar = A + (size_t)s_row * K + kb;
            pa0 = *(const float4*)(ar + s_c4 * 4);
            pa1 = *(const float4*)(ar + (s_c4 + 4) * 4);
            const float* wp = W + (size_t)kb * N + n0 + s_n;
#pragma unroll
            for (int j = 0; j < 8; j++) pb[j] = wp[(size_t)(s_k + j * 4) * N];
        }
        uint32_t aB = aAddr0 + (uint32_t)buf * 64 * SA * 4;
#pragma unroll
        for (int s = 0; s < 4; s++) {
            uint32_t a0, a1, a2, a3;
            LDMX4(a0, a1, a2, a3, aB + s * 32);
#pragma unroll
            for (int jp = 0; jp < 2; jp++) {
                uint32_t b0, b1, b2, b3;
                uint32_t baddr = bAddr0 + (uint32_t)buf * 64 * SA * 4 +
                                 (uint32_t)((wn * 32 + jp * 16 + b_row_off) * SA) * 4 + s * 32;
                LDMX4(b0, b1, b2, b3, baddr);
                mma_tf32(c[jp * 2], a0, a1, a2, a3, b0, b1);
                mma_tf32(c[jp * 2 + 1], a0, a1, a2, a3, b2, b3);
            }
        }
        if (st + 1 < nst) {
            int nb = buf ^ 1;
            uint4 u0 = make_uint4(f2tf(pa0.x), f2tf(pa0.y), f2tf(pa0.z), f2tf(pa0.w));
            uint4 u1 = make_uint4(f2tf(pa1.x), f2tf(pa1.y), f2tf(pa1.z), f2tf(pa1.w));
            *(uint4*)&As[nb][s_row * SA + s_c4 * 4] = u0;
            *(uint4*)&As[nb][s_row * SA + (s_c4 + 4) * 4] = u1;
#pragma unroll
            for (int j = 0; j < 8; j++)
                Bs[nb][s_n * SA + s_k + j * 4] = f2tf(pb[j]);
            __syncthreads();
        }
    }

    int g = lane >> 2, t = lane & 3;
    float* po = part + ((size_t)z * gridDim.y + slab) * MM * N;
#pragma unroll
    for (int j = 0; j < 4; j++) {
        int col = n0 + wn * 32 + j * 8 + 2 * t;
        int r0 = wm * 16 + g;
        *(float2*)&po[(size_t)r0 * N + col] = make_float2(c[j][0], c[j][1]);
        *(float2*)&po[(size_t)(r0 + 8) * N + col] = make_float2(c[j][2], c[j][3]);
    }
}

// ---------------- reduce partials + epilogue (multi-slab) ----------------
__global__ __launch_bounds__(256) void reduce_epi(const float* __restrict__ part, int nz,
                                                  int MN, int N,
                                                  const float* __restrict__ b0,
                                                  const float* __restrict__ b1,
                                                  const float* __restrict__ b2,
                                                  const float* __restrict__ res,
                                                  float* __restrict__ o0,
                                                  float* __restrict__ o1,
                                                  float* __restrict__ o2,
                                                  int dogelu) {
    int i = blockIdx.x * 256 + threadIdx.x;
    if (i >= MN) return;
    int slab = blockIdx.y;
    int nslab = gridDim.y;
    const float* bias = (slab == 0) ? b0 : ((slab == 1) ? b1 : b2);
    float* out = (slab == 0) ? o0 : ((slab == 1) ? o1 : o2);
    float s = 0.f;
    for (int z = 0; z < nz; z++) s += part[((size_t)z * nslab + slab) * MN + i];
    if (bias) s += bias[i % N];
    if (dogelu) s = 0.5f * s * (1.f + erff(s * 0.70710678118654752440f));
    if (res) s += res[i];
    out[i] = s;
}

// ---------------- attention split kernel (striped AV, cp.async tiles) ----
#define SCP 152
#define KTILE_F (32 * 68)     // floats per tile buffer
#define REDS 66               // reduce-buffer row stride (even -> float2 aligned)

__global__ __launch_bounds__(256) void attn_split(const float* __restrict__ kq,
                                                  const float* __restrict__ kc,
                                                  const float* __restrict__ vc,
                                                  const float* __restrict__ kn,
                                                  const float* __restrict__ vn,
                                                  const float* __restrict__ mask,
                                                  float* __restrict__ apacc,
                                                  float* __restrict__ aml,
                                                  int Tk, int Tc, int chunk) {
    __shared__ float sc[8 * SCP];
    __shared__ __align__(16) float kt[2][KTILE_F];
    __shared__ float qs[8 * 68];
    __shared__ float ml[16];

    int h = blockIdx.x, b = blockIdx.y, z = blockIdx.z;
    int k0 = z * chunk;
    int nv = min(Tk, k0 + chunk) - k0;
    int tid = threadIdx.x, lane = tid & 31, w = tid >> 5;
    uint32_t ktb = smem_to_u32(&kt[0][0]);

    if (tid < 128) {
        int qi = tid >> 4, d4 = (tid & 15) * 4;
        float4 v = *(const float4*)(kq + (size_t)(b * TQ + qi) * DD + h * DH + d4);
        v.x *= 0.125f; v.y *= 0.125f; v.z *= 0.125f; v.w *= 0.125f;
        *(float4*)&qs[qi * 68 + d4] = v;
    }
    __syncthreads();

    int qrow = lane >> 2, kslot = lane & 3;
    int krow = w * 4 + kslot;
    int s_key = tid >> 4, s_d4 = (tid & 15) * 4;      // staging: 2 iters/thread
    int nt = (nv + 31) >> 5;

    // ==== pass 1: scores ====
    {   // prologue: K tile 0 -> buf 0
        int nk0 = min(32, nv);
#pragma unroll
        for (int rep = 0; rep < 2; rep++) {
            int key = s_key + rep * 16;
            if (key < nk0) {
                int kg = k0 + key;
                const float* src = (kg < Tc)
                    ? kc + ((size_t)b * Tc + kg) * DD + h * DH
                    : kn + (size_t)(b * TQ + (kg - Tc)) * DD + h * DH;
                CP_ASYNC16(ktb + (uint32_t)(key * 68 + s_d4) * 4, src + s_d4);
            }
        }
        CP_COMMIT();
    }
    for (int t = 0; t < nt; t++) {
        int kb = t * 32;
        int nk = min(32, nv - kb);
        if (t + 1 < nt) {
            int kb2 = (t + 1) * 32;
            int nk2 = min(32, nv - kb2);
            uint32_t dst = ktb + (uint32_t)(((t + 1) & 1) * KTILE_F) * 4;
#pragma unroll
            for (int rep = 0; rep < 2; rep++) {
                int key = s_key + rep * 16;
                if (key < nk2) {
                    int kg = k0 + kb2 + key;
                    const float* src = (kg < Tc)
                        ? kc + ((size_t)b * Tc + kg) * DD + h * DH
                        : kn + (size_t)(b * TQ + (kg - Tc)) * DD + h * DH;
                    CP_ASYNC16(dst + (uint32_t)(key * 68 + s_d4) * 4, src + s_d4);
                }
            }
            CP_COMMIT();
            CP_WAIT1();
        } else {
            CP_WAIT0();
        }
        __syncthreads();
        if (krow < nk) {
            const float* qp = &qs[qrow * 68];
            const float* kp = &kt[t & 1][krow * 68];
            float acc = 0.f;
#pragma unroll
            for (int d = 0; d < 64; d += 4) {
                float4 qv = *(const float4*)(qp + d);
                float4 kv = *(const float4*)(kp + d);
                acc += qv.x * kv.x + qv.y * kv.y + qv.z * kv.z + qv.w * kv.w;
            }
            if (mask) acc += mask[(size_t)qrow * Tk + k0 + kb + krow];
            sc[qrow * SCP + kb + krow] = acc;
        }
        __syncthreads();
    }

    // ==== V tile 0 prefetch (into the buffer NOT used by the last K tile) ====
    // overlaps its DRAM latency with the softmax phase below
    {
        int nk0 = min(32, nv);
        uint32_t dst = ktb + (uint32_t)((nt & 1) * KTILE_F) * 4;
#pragma unroll
        for (int rep = 0; rep < 2; rep++) {
            int key = s_key + rep * 16;
            if (key < nk0) {
                int kg = k0 + key;
                const float* src = (kg < Tc)
                    ? vc + ((size_t)b * Tc + kg) * DD + h * DH
                    : vn + (size_t)(b * TQ + (kg - Tc)) * DD + h * DH;
                CP_ASYNC16(dst + (uint32_t)(key * 68 + s_d4) * 4, src + s_d4);
            }
        }
        CP_COMMIT();
    }

    // ==== partial softmax: warp w owns q row w ====
    {
        float m = -1e30f;
        for (int k = lane; k < nv; k += 32) m = fmaxf(m, sc[w * SCP + k]);
        for (int o = 16; o; o >>= 1) m = fmaxf(m, __shfl_xor_sync(~0u, m, o));
        float l = 0.f;
        for (int k = lane; k < nv; k += 32) {
            float e = __expf(sc[w * SCP + k] - m);
            sc[w * SCP + k] = e;
            l += e;
        }
        for (int o = 16; o; o >>= 1) l += __shfl_xor_sync(~0u, l, o);
        if (lane == 0) { ml[w * 2] = m; ml[w * 2 + 1] = l; }
    }
    __syncthreads();

    // ==== pass 2: AV, warp-striped keys (V read exactly once) ====
    float acc[8][2];
#pragma unroll
    for (int qi = 0; qi < 8; qi++) { acc[qi][0] = 0.f; acc[qi][1] = 0.f; }

    for (int t = 0; t < nt; t++) {
        int kb = t * 32;
        int nk = min(32, nv - kb);
        int cbuf = (t + nt) & 1;
        if (t + 1 < nt) {
            int kb2 = (t + 1) * 32;
            int nk2 = min(32, nv - kb2);
            uint32_t dst = ktb + (uint32_t)(((t + 1 + nt) & 1) * KTILE_F) * 4;
#pragma unroll
            for (int rep = 0; rep < 2; rep++) {
                int key = s_key + rep * 16;
                if (key < nk2) {
                    int kg = k0 + kb2 + key;
                    const float* src = (kg < Tc)
                        ? vc + ((size_t)b * Tc + kg) * DD + h * DH
                        : vn + (size_t)(b * TQ + (kg - Tc)) * DD + h * DH;
                    CP_ASYNC16(dst + (uint32_t)(key * 68 + s_d4) * 4, src + s_d4);
                }
            }
            CP_COMMIT();
            CP_WAIT1();
        } else {
            CP_WAIT0();
        }
        __syncthreads();
        const float* vt = &kt[cbuf][0];
        for (int k = w; k < nk; k += 8) {
            float2 v2 = *(const float2*)&vt[k * 68 + 2 * lane];
            const float* sp = &sc[kb + k];
#pragma unroll
            for (int qi = 0; qi < 8; qi++) {
                float p = sp[qi * SCP];
                acc[qi][0] += p * v2.x;
                acc[qi][1] += p * v2.y;
            }
        }
        __syncthreads();
    }

    // ==== cross-warp reduce (buffer aliased onto kt; all tiles consumed) ====
    float* red = (float*)&kt[0][0];   // 64 rows x REDS floats = 16.9KB < 17.4KB
#pragma unroll
    for (int qi = 0; qi < 8; qi++)
        *(float2*)&red[(w * 8 + qi) * REDS + 2 * lane] = make_float2(acc[qi][0], acc[qi][1]);
    __syncthreads();

    size_t idx = ((size_t)z * BB + b) * HH + h;
    float* ap = apacc + idx * TQ * DH;
    int qi2 = tid >> 5, dp = tid & 31;
    float s0 = 0.f, s1 = 0.f;
#pragma unroll
    for (int ww = 0; ww < 8; ww++) {
        float2 a = *(const float2*)&red[(ww * 8 + qi2) * REDS + 2 * dp];
        s0 += a.x;
        s1 += a.y;
    }
    *(float2*)&ap[qi2 * 64 + 2 * dp] = make_float2(s0, s1);
    if (tid < 16) aml[idx * 16 + tid] = ml[tid];
}

// ---------------- attention combine ----------------
__global__ __launch_bounds__(256) void attn_combine(const float* __restrict__ apacc,
                                                    const float* __restrict__ aml,
                                                    float* __restrict__ out, int S) {
    int h = blockIdx.x, b = blockIdx.y;
    int tid = threadIdx.x;
    int qi = tid >> 5, dp = tid & 31;
    float mstar = -1e30f;
    for (int z = 0; z < S; z++) {
        size_t idx = ((size_t)z * BB + b) * HH + h;
        mstar = fmaxf(mstar, aml[idx * 16 + qi * 2]);
    }
    float den = 0.f, n0 = 0.f, n1 = 0.f;
    for (int z = 0; z < S; z++) {
        size_t idx = ((size_t)z * BB + b) * HH + h;
        float mz = aml[idx * 16 + qi * 2];
        float lz = aml[idx * 16 + qi * 2 + 1];
        float s = __expf(mz - mstar);
        den += lz * s;
        float2 a = *(const float2*)&apacc[idx * TQ * DH + qi * 64 + dp * 2];
        n0 += a.x * s;
        n1 += a.y * s;
    }
    float inv = 1.f / den;
    float* o = out + (size_t)(b * TQ + qi) * DD + h * DH + dp * 2;
    o[0] = n0 * inv;
    o[1] = n1 * inv;
}

// ---------------- host orchestration ----------------
extern "C" void kernel_launch(void* const* d_in, const int* in_sizes, int n_in,
                              void* d_out, int out_size) {
    const float* x            = (const float*)d_in[0];
    const float* self_k_cache = (const float*)d_in[1];
    const float* self_v_cache = (const float*)d_in[2];
    const float* cross_k      = (const float*)d_in[3];
    const float* cross_v      = (const float*)d_in[4];
    const float* mask         = (const float*)d_in[5];
    const float* attn_wq = (const float*)d_in[6];
    const float* attn_bq = (const float*)d_in[7];
    const float* attn_wk = (const float*)d_in[8];
    const float* attn_wv = (const float*)d_in[9];
    const float* attn_bv = (const float*)d_in[10];
    const float* attn_wo = (const float*)d_in[11];
    const float* attn_bo = (const float*)d_in[12];
    const float* cross_wq = (const float*)d_in[13];
    const float* cross_bq = (const float*)d_in[14];
    const float* cross_wo = (const float*)d_in[15];
    const float* cross_bo = (const float*)d_in[16];
    const float* attn_ln_w = (const float*)d_in[17];
    const float* attn_ln_b = (const float*)d_in[18];
    const float* cross_ln_w = (const float*)d_in[19];
    const float* cross_ln_b = (const float*)d_in[20];
    const float* mlp_ln_w = (const float*)d_in[21];
    const float* mlp_ln_b = (const float*)d_in[22];
    const float* mlp_w1 = (const float*)d_in[23];
    const float* mlp_b1 = (const float*)d_in[24];
    const float* mlp_w2 = (const float*)d_in[25];
    const float* mlp_b2 = (const float*)d_in[26];

    float* out_x  = (float*)d_out;
    float* out_k1 = out_x + MM * DD;
    float* out_v1 = out_k1 + MM * DD;

    float *g_xl, *g_q, *g_attn, *g_x1, *g_h, *g_part, *g_apacc, *g_aml;
    cudaGetSymbolAddress((void**)&g_xl, g_xl_);
    cudaGetSymbolAddress((void**)&g_q, g_q_);
    cudaGetSymbolAddress((void**)&g_attn, g_attn_);
    cudaGetSymbolAddress((void**)&g_x1, g_x1_);
    cudaGetSymbolAddress((void**)&g_h, g_h_);
    cudaGetSymbolAddress((void**)&g_part, g_part_);
    cudaGetSymbolAddress((void**)&g_apacc, g_apacc_);
    cudaGetSymbolAddress((void**)&g_aml, g_aml_);

    const int MN_D = MM * DD;        // 81920
    const int MN_F = MM * DFF;       // 327680
    dim3 blk(256);

    dim3 gQKV(DD / 64, 3, 10);   // fused QKV: kc=128 (4 stages), 600 CTAs
    dim3 gD(DD / 64, 1, 20);     // D GEMM: kc=64 (2 stages), 400 CTAs
    dim3 gF1(DFF / 64, 1, 8);    // MLP1: kc=160 (5 stages), 640 CTAs
    dim3 gF2(DD / 64, 1, 20);    // MLP2: kc=256 (8 stages), 400 CTAs
    int redD = (MN_D + 255) / 256;
    int redF = (MN_F + 255) / 256;

    int S_SELF = 6, CH_SELF = (TK_SELF + S_SELF - 1) / S_SELF;   // 76
    int S_CROSS = 10, CH_CROSS = TC / S_CROSS;                   // 150

    // --- self-attention block ---
    ln_kernel<<<MM, blk>>>(x, attn_ln_w, attn_ln_b, g_xl);

    gemm_mma<<<gQKV, blk>>>(g_xl, attn_wq, attn_wk, attn_wv, g_part, DD, DD, 128);
    reduce_epi<<<dim3(redD, 3), blk>>>(g_part, 10, MN_D, DD,
                                       attn_bq, nullptr, attn_bv, nullptr,
                                       g_q, out_k1, out_v1, 0);

    attn_split<<<dim3(HH, BB, S_SELF), blk>>>(g_q, self_k_cache, self_v_cache,
                                              out_k1, out_v1, mask,
                                              g_apacc, g_aml, TK_SELF, TP, CH_SELF);
    attn_combine<<<dim3(HH, BB), blk>>>(g_apacc, g_aml, g_attn, S_SELF);

    gemm_mma<<<gD, blk>>>(g_attn, attn_wo, attn_wo, attn_wo, g_part, DD, DD, 64);
    reduce_epi<<<dim3(redD, 1), blk>>>(g_part, 20, MN_D, DD,
                                       attn_bo, nullptr, nullptr, x,
                                       g_x1, nullptr, nullptr, 0);

    // --- cross-attention block ---
    ln_kernel<<<MM, blk>>>(g_x1, cross_ln_w, cross_ln_b, g_xl);

    gemm_mma<<<gD, blk>>>(g_xl, cross_wq, cross_wq, cross_wq, g_part, DD, DD, 64);
    reduce_epi<<<dim3(redD, 1), blk>>>(g_part, 20, MN_D, DD,
                                       cross_bq, nullptr, nullptr, nullptr,
                                       g_q, nullptr, nullptr, 0);

    attn_split<<<dim3(HH, BB, S_CROSS), blk>>>(g_q, cross_k, cross_v,
                                               nullptr, nullptr, nullptr,
                                               g_apacc, g_aml, TC, TC, CH_CROSS);
    attn_combine<<<dim3(HH, BB), blk>>>(g_apacc, g_aml, g_attn, S_CROSS);

    gemm_mma<<<gD, blk>>>(g_attn, cross_wo, cross_wo, cross_wo, g_part, DD, DD, 64);
    reduce_epi<<<dim3(redD, 1), blk>>>(g_part, 20, MN_D, DD,
                                       cross_bo, nullptr, nullptr, g_x1,
                                       out_x, nullptr, nullptr, 0);

    // --- MLP block ---
    ln_kernel<<<MM, blk>>>(out_x, mlp_ln_w, mlp_ln_b, g_xl);

    gemm_mma<<<gF1, blk>>>(g_xl, mlp_w1, mlp_w1, mlp_w1, g_part, DD, DFF, 160);
    reduce_epi<<<dim3(redF, 1), blk>>>(g_part, 8, MN_F, DFF,
                                       mlp_b1, nullptr, nullptr, nullptr,
                                       g_h, nullptr, nullptr, 1);

    gemm_mma<<<gF2, blk>>>(g_h, mlp_w2, mlp_w2, mlp_w2, g_part, DFF, DD, 256);
    reduce_epi<<<dim3(redD, 1), blk>>>(g_part, 20, MN_D, DD,
                                       mlp_b2, nullptr, nullptr, out_x,
                                       out_x, nullptr, nullptr, 0);
}

// round 12
// speedup vs baseline: 2.3611x; 1.0336x over previous
#include <cuda_runtime.h>
#include <cuda_bf16.h>
#include <cstdint>
#include <math.h>

// ---------------- problem constants ----------------
#define BB 8
#define TQ 8
#define TP 447
#define TC 1500
#define DD 1280
#define HH 20
#define DH 64
#define DFF 5120
#define MM 64              // B*TQ rows
#define TK_SELF (TP + TQ)  // 455

// ---------------- scratch (device globals; no allocation allowed) ----------------
__device__ float g_xl_[MM * DD];
__device__ float g_q_[MM * DD];
__device__ float g_attn_[MM * DD];
__device__ float g_x1_[MM * DD];
__device__ float g_h_[MM * DFF];
__device__ float g_part_[4915200];                  // split-K partials
__device__ float g_apacc_[16 * BB * HH * TQ * DH];  // attn split partial acc
__device__ float g_aml_[16 * BB * HH * 16];         // attn split (m,l) per q

// ---------------- helpers ----------------
__device__ __forceinline__ uint32_t smem_to_u32(const void* p) {
    uint32_t a;
    asm("{ .reg .u64 t; cvta.to.shared.u64 t, %1; cvt.u32.u64 %0, t; }" : "=r"(a) : "l"(p));
    return a;
}
__device__ __forceinline__ uint32_t f2tf(float f) {
    uint32_t r;
    asm("cvt.rna.tf32.f32 %0, %1;" : "=r"(r) : "f"(f));
    return r;
}
#define LDMX4(r0, r1, r2, r3, addr) \
    asm volatile("ldmatrix.sync.aligned.m8n8.x4.shared.b16 {%0,%1,%2,%3}, [%4];" \
                 : "=r"(r0), "=r"(r1), "=r"(r2), "=r"(r3) : "r"(addr))
__device__ __forceinline__ void mma_tf32(float c[4], uint32_t a0, uint32_t a1,
                                         uint32_t a2, uint32_t a3,
                                         uint32_t b0, uint32_t b1) {
    asm volatile(
        "mma.sync.aligned.m16n8k8.row.col.f32.tf32.tf32.f32 "
        "{%0,%1,%2,%3}, {%4,%5,%6,%7}, {%8,%9}, {%0,%1,%2,%3};"
        : "+f"(c[0]), "+f"(c[1]), "+f"(c[2]), "+f"(c[3])
        : "r"(a0), "r"(a1), "r"(a2), "r"(a3), "r"(b0), "r"(b1));
}
#define CP_ASYNC16(saddr, gptr) \
    asm volatile("cp.async.cg.shared.global [%0], [%1], 16;" :: "r"(saddr), "l"(gptr))
#define CP_COMMIT() asm volatile("cp.async.commit_group;" ::: "memory")
#define CP_WAIT1() asm volatile("cp.async.wait_group 1;" ::: "memory")
#define CP_WAIT0() asm volatile("cp.async.wait_group 0;" ::: "memory")

// ---------------- LayerNorm: one block per row ----------------
__global__ __launch_bounds__(256) void ln_kernel(const float* __restrict__ x,
                                                 const float* __restrict__ w,
                                                 const float* __restrict__ b,
                                                 float* __restrict__ out) {
    int row = blockIdx.x;
    const float* xr = x + (size_t)row * DD;
    __shared__ float red0[32], red1[32];
    float s = 0.f, s2 = 0.f;
    for (int i = threadIdx.x; i < DD; i += 256) {
        float v = xr[i];
        s += v;
        s2 += v * v;
    }
    for (int o = 16; o; o >>= 1) {
        s += __shfl_xor_sync(~0u, s, o);
        s2 += __shfl_xor_sync(~0u, s2, o);
    }
    int lane = threadIdx.x & 31, wid = threadIdx.x >> 5;
    if (lane == 0) { red0[wid] = s; red1[wid] = s2; }
    __syncthreads();
    if (wid == 0) {
        s = (lane < 8) ? red0[lane] : 0.f;
        s2 = (lane < 8) ? red1[lane] : 0.f;
        for (int o = 4; o; o >>= 1) {
            s += __shfl_xor_sync(~0u, s, o);
            s2 += __shfl_xor_sync(~0u, s2, o);
        }
        if (lane == 0) { red0[0] = s; red1[0] = s2; }
    }
    __syncthreads();
    float m = red0[0] * (1.f / DD);
    float var = red1[0] * (1.f / DD) - m * m;
    float inv = rsqrtf(var + 1e-5f);
    for (int i = threadIdx.x; i < DD; i += 256) {
        out[(size_t)row * DD + i] = (xr[i] - m) * inv * w[i] + b[i];
    }
}

// ---------------- mma.sync tf32 split-K GEMM ----------------
#define SA 36   // smem row stride in floats

__global__ __launch_bounds__(256) void gemm_mma(const float* __restrict__ A,
                                                const float* __restrict__ W0,
                                                const float* __restrict__ W1,
                                                const float* __restrict__ W2,
                                                float* __restrict__ part,
                                                int K, int N, int kc) {
    __shared__ __align__(16) uint32_t As[2][64 * SA];
    __shared__ __align__(16) uint32_t Bs[2][64 * SA];
    int tid = threadIdx.x, lane = tid & 31, w = tid >> 5;
    int wm = w & 3, wn = w >> 2;
    int n0 = blockIdx.x * 64;
    int slab = blockIdx.y;
    const float* W = (slab == 0) ? W0 : ((slab == 1) ? W1 : W2);
    int z = blockIdx.z, k0 = z * kc;
    int nst = kc >> 5;

    int a_row = wm * 16 + ((lane >> 3) & 1) * 8 + (lane & 7);
    uint32_t a_koff = ((lane >> 4) & 1) * 16;
    int b_row_off = ((lane >> 4) & 1) * 8 + (lane & 7);
    uint32_t b_koff = ((lane >> 3) & 1) * 16;
    uint32_t aAddr0 = smem_to_u32(&As[0][0]) + (uint32_t)(a_row * SA) * 4 + a_koff;
    uint32_t bAddr0 = smem_to_u32(&Bs[0][0]) + b_koff;

    int s_row = tid >> 2, s_c4 = tid & 3;
    int s_n = tid & 63, s_k = tid >> 6;

    float c[4][4];
#pragma unroll
    for (int j = 0; j < 4; j++)
#pragma unroll
        for (int i = 0; i < 4; i++) c[j][i] = 0.f;

    {
        const float* ar = A + (size_t)s_row * K + k0;
        float4 v0 = *(const float4*)(ar + s_c4 * 4);
        float4 v1 = *(const float4*)(ar + (s_c4 + 4) * 4);
        uint4 u0 = make_uint4(f2tf(v0.x), f2tf(v0.y), f2tf(v0.z), f2tf(v0.w));
        uint4 u1 = make_uint4(f2tf(v1.x), f2tf(v1.y), f2tf(v1.z), f2tf(v1.w));
        *(uint4*)&As[0][s_row * SA + s_c4 * 4] = u0;
        *(uint4*)&As[0][s_row * SA + (s_c4 + 4) * 4] = u1;
        const float* wp = W + (size_t)k0 * N + n0 + s_n;
#pragma unroll
        for (int j = 0; j < 8; j++) {
            int k2 = s_k + j * 4;
            Bs[0][s_n * SA + k2] = f2tf(wp[(size_t)k2 * N]);
        }
    }
    __syncthreads();

    for (int st = 0; st < nst; st++) {
        int buf = st & 1;
        float4 pa0, pa1;
        float pb[8];
        if (st + 1 < nst) {
            int kb = k0 + (st + 1) * 32;
            const float* ar = A + (size_t)s_row * K + kb;
            pa0 = *(const float4*)(ar + s_c4 * 4);
            pa1 = *(const float4*)(ar + (s_c4 + 4) * 4);
            const float* wp = W + (size_t)kb * N + n0 + s_n;
#pragma unroll
            for (int j = 0; j < 8; j++) pb[j] = wp[(size_t)(s_k + j * 4) * N];
        }
        uint32_t aB = aAddr0 + (uint32_t)buf * 64 * SA * 4;
#pragma unroll
        for (int s = 0; s < 4; s++) {
            uint32_t a0, a1, a2, a3;
            LDMX4(a0, a1, a2, a3, aB + s * 32);
#pragma unroll
            for (int jp = 0; jp < 2; jp++) {
                uint32_t b0, b1, b2, b3;
                uint32_t baddr = bAddr0 + (uint32_t)buf * 64 * SA * 4 +
                                 (uint32_t)((wn * 32 + jp * 16 + b_row_off) * SA) * 4 + s * 32;
                LDMX4(b0, b1, b2, b3, baddr);
                mma_tf32(c[jp * 2], a0, a1, a2, a3, b0, b1);
                mma_tf32(c[jp * 2 + 1], a0, a1, a2, a3, b2, b3);
            }
        }
        if (st + 1 < nst) {
            int nb = buf ^ 1;
            uint4 u0 = make_uint4(f2tf(pa0.x), f2tf(pa0.y), f2tf(pa0.z), f2tf(pa0.w));
            uint4 u1 = make_uint4(f2tf(pa1.x), f2tf(pa1.y), f2tf(pa1.z), f2tf(pa1.w));
            *(uint4*)&As[nb][s_row * SA + s_c4 * 4] = u0;
            *(uint4*)&As[nb][s_row * SA + (s_c4 + 4) * 4] = u1;
#pragma unroll
            for (int j = 0; j < 8; j++)
                Bs[nb][s_n * SA + s_k + j * 4] = f2tf(pb[j]);
            __syncthreads();
        }
    }

    int g = lane >> 2, t = lane & 3;
    float* po = part + ((size_t)z * gridDim.y + slab) * MM * N;
#pragma unroll
    for (int j = 0; j < 4; j++) {
        int col = n0 + wn * 32 + j * 8 + 2 * t;
        int r0 = wm * 16 + g;
        *(float2*)&po[(size_t)r0 * N + col] = make_float2(c[j][0], c[j][1]);
        *(float2*)&po[(size_t)(r0 + 8) * N + col] = make_float2(c[j][2], c[j][3]);
    }
}

// ---------------- reduce partials + epilogue (multi-slab) ----------------
__global__ __launch_bounds__(256) void reduce_epi(const float* __restrict__ part, int nz,
                                                  int MN, int N,
                                                  const float* __restrict__ b0,
                                                  const float* __restrict__ b1,
                                                  const float* __restrict__ b2,
                                                  const float* __restrict__ res,
                                                  float* __restrict__ o0,
                                                  float* __restrict__ o1,
                                                  float* __restrict__ o2,
                                                  int dogelu) {
    int i = blockIdx.x * 256 + threadIdx.x;
    if (i >= MN) return;
    int slab = blockIdx.y;
    int nslab = gridDim.y;
    const float* bias = (slab == 0) ? b0 : ((slab == 1) ? b1 : b2);
    float* out = (slab == 0) ? o0 : ((slab == 1) ? o1 : o2);
    float s = 0.f;
    for (int z = 0; z < nz; z++) s += part[((size_t)z * nslab + slab) * MN + i];
    if (bias) s += bias[i % N];
    if (dogelu) s = 0.5f * s * (1.f + erff(s * 0.70710678118654752440f));
    if (res) s += res[i];
    out[i] = s;
}

// ---------------- attention split kernel (mma scores + striped AV) ----------
#define SCP 152
#define ATILE 64
#define KT_F (ATILE * 68)     // floats per tile buffer
#define REDS 66               // reduce-buffer row stride

// stage one 64-key tile (cp.async); each thread: 4 x 16B of one key row
__device__ __forceinline__ void stage_tile(uint32_t dst, const float* cache,
                                           const float* neu, int b, int h, int Tc,
                                           int kgbase, int nk, int srow, int sq4) {
    if (srow < nk) {
        int kg = kgbase + srow;
        const float* src = (kg < Tc)
            ? cache + ((size_t)b * Tc + kg) * DD + h * DH
            : neu + (size_t)(b * TQ + (kg - Tc)) * DD + h * DH;
        uint32_t d = dst + (uint32_t)(srow * 68) * 4;
#pragma unroll
        for (int j = 0; j < 4; j++)
            CP_ASYNC16(d + (uint32_t)((sq4 + j) * 16), src + (sq4 + j) * 4);
    }
}

__global__ __launch_bounds__(256) void attn_split(const float* __restrict__ kq,
                                                  const float* __restrict__ kc,
                                                  const float* __restrict__ vc,
                                                  const float* __restrict__ kn,
                                                  const float* __restrict__ vn,
                                                  const float* __restrict__ mask,
                                                  float* __restrict__ apacc,
                                                  float* __restrict__ aml,
                                                  int Tk, int Tc, int chunk) {
    __shared__ float sc[8 * SCP];
    __shared__ __align__(16) float kt[2][KT_F];
    __shared__ float qs[8 * 68];
    __shared__ float ml[16];

    int h = blockIdx.x, b = blockIdx.y, z = blockIdx.z;
    int k0 = z * chunk;
    int nv = min(Tk, k0 + chunk) - k0;
    int tid = threadIdx.x, lane = tid & 31, w = tid >> 5;
    uint32_t ktb = smem_to_u32(&kt[0][0]);

    if (tid < 128) {
        int qi = tid >> 4, d4 = (tid & 15) * 4;
        float4 v = *(const float4*)(kq + (size_t)(b * TQ + qi) * DD + h * DH + d4);
        v.x *= 0.125f; v.y *= 0.125f; v.z *= 0.125f; v.w *= 0.125f;
        *(float4*)&qs[qi * 68 + d4] = v;
    }
    __syncthreads();

    // A fragments: q rows 0..7 (rows 8..15 of m16 are zero)
    uint32_t aA[8], aC[8];
    const uint32_t zr = 0;
    {
        const float* qp = &qs[(lane >> 2) * 68];
#pragma unroll
        for (int s = 0; s < 8; s++) {
            aA[s] = f2tf(qp[s * 8 + (lane & 3)]);
            aC[s] = f2tf(qp[s * 8 + 4 + (lane & 3)]);
        }
    }

    int srow = tid >> 2, sq4 = (tid & 3) * 4;
    int nt = (nv + ATILE - 1) / ATILE;
    // ldmatrix base: warp w's 8 key rows; 4 matrices span 64B of k-dim
    uint32_t kfrag_off = (uint32_t)((w * 8 + (lane & 7)) * 68) * 4 + ((lane >> 3) & 3) * 16;

    // ==== pass 1: scores via mma ====
    stage_tile(ktb, kc, kn, b, h, Tc, k0, min(ATILE, nv), srow, sq4);
    CP_COMMIT();
    for (int t = 0; t < nt; t++) {
        int kb = t * ATILE;
        int nk = min(ATILE, nv - kb);
        if (t + 1 < nt) {
            stage_tile(ktb + (uint32_t)(((t + 1) & 1) * KT_F) * 4, kc, kn, b, h, Tc,
                       k0 + kb + ATILE, min(ATILE, nv - kb - ATILE), srow, sq4);
            CP_COMMIT();
            CP_WAIT1();
        } else {
            CP_WAIT0();
        }
        __syncthreads();
        float c0[4] = {0.f, 0.f, 0.f, 0.f};
        uint32_t kaddr = ktb + (uint32_t)((t & 1) * KT_F) * 4 + kfrag_off;
#pragma unroll
        for (int s = 0; s < 4; s++) {
            uint32_t b0, b1, b2, b3;
            LDMX4(b0, b1, b2, b3, kaddr + s * 64);
            mma_tf32(c0, aA[2 * s], zr, aC[2 * s], zr, b0, b1);
            mma_tf32(c0, aA[2 * s + 1], zr, aC[2 * s + 1], zr, b2, b3);
        }
        int qrow = lane >> 2;
        int key = w * 8 + 2 * (lane & 3);
        if (key < nk) {
            float s0 = c0[0];
            if (mask) s0 += mask[(size_t)qrow * Tk + k0 + kb + key];
            sc[qrow * SCP + kb + key] = s0;
        }
        if (key + 1 < nk) {
            float s1 = c0[1];
            if (mask) s1 += mask[(size_t)qrow * Tk + k0 + kb + key + 1];
            sc[qrow * SCP + kb + key + 1] = s1;
        }
        __syncthreads();
    }

    // ==== V tile 0 prefetch (buffer not holding last K tile); hides under softmax
    stage_tile(ktb + (uint32_t)((nt & 1) * KT_F) * 4, vc, vn, b, h, Tc,
               k0, min(ATILE, nv), srow, sq4);
    CP_COMMIT();

    // ==== partial softmax: warp w owns q row w ====
    {
        float m = -1e30f;
        for (int k = lane; k < nv; k += 32) m = fmaxf(m, sc[w * SCP + k]);
        for (int o = 16; o; o >>= 1) m = fmaxf(m, __shfl_xor_sync(~0u, m, o));
        float l = 0.f;
        for (int k = lane; k < nv; k += 32) {
            float e = __expf(sc[w * SCP + k] - m);
            sc[w * SCP + k] = e;
            l += e;
        }
        for (int o = 16; o; o >>= 1) l += __shfl_xor_sync(~0u, l, o);
        if (lane == 0) { ml[w * 2] = m; ml[w * 2 + 1] = l; }
    }
    __syncthreads();

    // ==== pass 2: AV, warp-striped keys (V read exactly once) ====
    float acc[8][2];
#pragma unroll
    for (int qi = 0; qi < 8; qi++) { acc[qi][0] = 0.f; acc[qi][1] = 0.f; }

    for (int t = 0; t < nt; t++) {
        int kb = t * ATILE;
        int nk = min(ATILE, nv - kb);
        int cbuf = (t + nt) & 1;
        if (t + 1 < nt) {
            stage_tile(ktb + (uint32_t)(((t + 1 + nt) & 1) * KT_F) * 4, vc, vn, b, h, Tc,
                       k0 + kb + ATILE, min(ATILE, nv - kb - ATILE), srow, sq4);
            CP_COMMIT();
            CP_WAIT1();
        } else {
            CP_WAIT0();
        }
        __syncthreads();
        const float* vt = &kt[cbuf][0];
        for (int k = w; k < nk; k += 8) {
            float2 v2 = *(const float2*)&vt[k * 68 + 2 * lane];
            const float* sp = &sc[kb + k];
#pragma unroll
            for (int qi = 0; qi < 8; qi++) {
                float p = sp[qi * SCP];
                acc[qi][0] += p * v2.x;
                acc[qi][1] += p * v2.y;
            }
        }
        __syncthreads();
    }

    // ==== cross-warp reduce (buffer aliased onto kt[0]) ====
    float* red = (float*)&kt[0][0];   // 64 x REDS floats = 16.9KB <= 17.4KB
#pragma unroll
    for (int qi = 0; qi < 8; qi++)
        *(float2*)&red[(w * 8 + qi) * REDS + 2 * lane] = make_float2(acc[qi][0], acc[qi][1]);
    __syncthreads();

    size_t idx = ((size_t)z * BB + b) * HH + h;
    float* ap = apacc + idx * TQ * DH;
    int qi2 = tid >> 5, dp = tid & 31;
    float s0 = 0.f, s1 = 0.f;
#pragma unroll
    for (int ww = 0; ww < 8; ww++) {
        float2 a = *(const float2*)&red[(ww * 8 + qi2) * REDS + 2 * dp];
        s0 += a.x;
        s1 += a.y;
    }
    *(float2*)&ap[qi2 * 64 + 2 * dp] = make_float2(s0, s1);
    if (tid < 16) aml[idx * 16 + tid] = ml[tid];
}

// ---------------- attention combine ----------------
__global__ __launch_bounds__(256) void attn_combine(const float* __restrict__ apacc,
                                                    const float* __restrict__ aml,
                                                    float* __restrict__ out, int S) {
    int h = blockIdx.x, b = blockIdx.y;
    int tid = threadIdx.x;
    int qi = tid >> 5, dp = tid & 31;
    float mstar = -1e30f;
    for (int z = 0; z < S; z++) {
        size_t idx = ((size_t)z * BB + b) * HH + h;
        mstar = fmaxf(mstar, aml[idx * 16 + qi * 2]);
    }
    float den = 0.f, n0 = 0.f, n1 = 0.f;
    for (int z = 0; z < S; z++) {
        size_t idx = ((size_t)z * BB + b) * HH + h;
        float mz = aml[idx * 16 + qi * 2];
        float lz = aml[idx * 16 + qi * 2 + 1];
        float s = __expf(mz - mstar);
        den += lz * s;
        float2 a = *(const float2*)&apacc[idx * TQ * DH + qi * 64 + dp * 2];
        n0 += a.x * s;
        n1 += a.y * s;
    }
    float inv = 1.f / den;
    float* o = out + (size_t)(b * TQ + qi) * DD + h * DH + dp * 2;
    o[0] = n0 * inv;
    o[1] = n1 * inv;
}

// ---------------- host orchestration ----------------
extern "C" void kernel_launch(void* const* d_in, const int* in_sizes, int n_in,
                              void* d_out, int out_size) {
    const float* x            = (const float*)d_in[0];
    const float* self_k_cache = (const float*)d_in[1];
    const float* self_v_cache = (const float*)d_in[2];
    const float* cross_k      = (const float*)d_in[3];
    const float* cross_v      = (const float*)d_in[4];
    const float* mask         = (const float*)d_in[5];
    const float* attn_wq = (const float*)d_in[6];
    const float* attn_bq = (const float*)d_in[7];
    const float* attn_wk = (const float*)d_in[8];
    const float* attn_wv = (const float*)d_in[9];
    const float* attn_bv = (const float*)d_in[10];
    const float* attn_wo = (const float*)d_in[11];
    const float* attn_bo = (const float*)d_in[12];
    const float* cross_wq = (const float*)d_in[13];
    const float* cross_bq = (const float*)d_in[14];
    const float* cross_wo = (const float*)d_in[15];
    const float* cross_bo = (const float*)d_in[16];
    const float* attn_ln_w = (const float*)d_in[17];
    const float* attn_ln_b = (const float*)d_in[18];
    const float* cross_ln_w = (const float*)d_in[19];
    const float* cross_ln_b = (const float*)d_in[20];
    const float* mlp_ln_w = (const float*)d_in[21];
    const float* mlp_ln_b = (const float*)d_in[22];
    const float* mlp_w1 = (const float*)d_in[23];
    const float* mlp_b1 = (const float*)d_in[24];
    const float* mlp_w2 = (const float*)d_in[25];
    const float* mlp_b2 = (const float*)d_in[26];

    float* out_x  = (float*)d_out;
    float* out_k1 = out_x + MM * DD;
    float* out_v1 = out_k1 + MM * DD;

    float *g_xl, *g_q, *g_attn, *g_x1, *g_h, *g_part, *g_apacc, *g_aml;
    cudaGetSymbolAddress((void**)&g_xl, g_xl_);
    cudaGetSymbolAddress((void**)&g_q, g_q_);
    cudaGetSymbolAddress((void**)&g_attn, g_attn_);
    cudaGetSymbolAddress((void**)&g_x1, g_x1_);
    cudaGetSymbolAddress((void**)&g_h, g_h_);
    cudaGetSymbolAddress((void**)&g_part, g_part_);
    cudaGetSymbolAddress((void**)&g_apacc, g_apacc_);
    cudaGetSymbolAddress((void**)&g_aml, g_aml_);

    const int MN_D = MM * DD;        // 81920
    const int MN_F = MM * DFF;       // 327680
    dim3 blk(256);

    dim3 gQKV(DD / 64, 3, 10);   // fused QKV: kc=128 (4 stages), 600 CTAs
    dim3 gD(DD / 64, 1, 20);     // D GEMM: kc=64 (2 stages), 400 CTAs
    dim3 gF1(DFF / 64, 1, 8);    // MLP1: kc=160 (5 stages), 640 CTAs
    dim3 gF2(DD / 64, 1, 20);    // MLP2: kc=256 (8 stages), 400 CTAs
    int redD = (MN_D + 255) / 256;
    int redF = (MN_F + 255) / 256;

    int S_SELF = 8, CH_SELF = (TK_SELF + S_SELF - 1) / S_SELF;   // 57 (1 tile)
    int S_CROSS = 12, CH_CROSS = (TC + S_CROSS - 1) / S_CROSS;   // 125 (2 tiles)

    // --- self-attention block ---
    ln_kernel<<<MM, blk>>>(x, attn_ln_w, attn_ln_b, g_xl);

    gemm_mma<<<gQKV, blk>>>(g_xl, attn_wq, attn_wk, attn_wv, g_part, DD, DD, 128);
    reduce_epi<<<dim3(redD, 3), blk>>>(g_part, 10, MN_D, DD,
                                       attn_bq, nullptr, attn_bv, nullptr,
                                       g_q, out_k1, out_v1, 0);

    attn_split<<<dim3(HH, BB, S_SELF), blk>>>(g_q, self_k_cache, self_v_cache,
                                              out_k1, out_v1, mask,
                                              g_apacc, g_aml, TK_SELF, TP, CH_SELF);
    attn_combine<<<dim3(HH, BB), blk>>>(g_apacc, g_aml, g_attn, S_SELF);

    gemm_mma<<<gD, blk>>>(g_attn, attn_wo, attn_wo, attn_wo, g_part, DD, DD, 64);
    reduce_epi<<<dim3(redD, 1), blk>>>(g_part, 20, MN_D, DD,
                                       attn_bo, nullptr, nullptr, x,
                                       g_x1, nullptr, nullptr, 0);

    // --- cross-attention block ---
    ln_kernel<<<MM, blk>>>(g_x1, cross_ln_w, cross_ln_b, g_xl);

    gemm_mma<<<gD, blk>>>(g_xl, cross_wq, cross_wq, cross_wq, g_part, DD, DD, 64);
    reduce_epi<<<dim3(redD, 1), blk>>>(g_part, 20, MN_D, DD,
                                       cross_bq, nullptr, nullptr, nullptr,
                                       g_q, nullptr, nullptr, 0);

    attn_split<<<dim3(HH, BB, S_CROSS), blk>>>(g_q, cross_k, cross_v,
                                               nullptr, nullptr, nullptr,
                                               g_apacc, g_aml, TC, TC, CH_CROSS);
    attn_combine<<<dim3(HH, BB), blk>>>(g_apacc, g_aml, g_attn, S_CROSS);

    gemm_mma<<<gD, blk>>>(g_attn, cross_wo, cross_wo, cross_wo, g_part, DD, DD, 64);
    reduce_epi<<<dim3(redD, 1), blk>>>(g_part, 20, MN_D, DD,
                                       cross_bo, nullptr, nullptr, g_x1,
                                       out_x, nullptr, nullptr, 0);

    // --- MLP block ---
    ln_kernel<<<MM, blk>>>(out_x, mlp_ln_w, mlp_ln_b, g_xl);

    gemm_mma<<<gF1, blk>>>(g_xl, mlp_w1, mlp_w1, mlp_w1, g_part, DD, DFF, 160);
    reduce_epi<<<dim3(redF, 1), blk>>>(g_part, 8, MN_F, DFF,
                                       mlp_b1, nullptr, nullptr, nullptr,
                                       g_h, nullptr, nullptr, 1);

    gemm_mma<<<gF2, blk>>>(g_h, mlp_w2, mlp_w2, mlp_w2, g_part, DFF, DD, 256);
    reduce_epi<<<dim3(redD, 1), blk>>>(g_part, 20, MN_D, DD,
                                       mlp_b2, nullptr, nullptr, out_x,
                                       out_x, nullptr, nullptr, 0);
}